// round 13
// baseline (speedup 1.0000x reference)
#include <cuda_runtime.h>
#include <cuda_bf16.h>
#include <math.h>
#include <stdint.h>

// Problem constants
#define BB   2
#define SS   2048
#define DD   1024
#define HH   16
#define HDIM 64
#define DFFN 4096
#define ROWS (BB * SS)   // 4096

// -------- scratch (static device globals; no allocation) --------
__device__ __align__(16) __nv_bfloat16 g_h_hi[ROWS * DD], g_h_lo[ROWS * DD];
__device__ __align__(16) __nv_bfloat16 g_qkvh[ROWS * 3 * DD], g_qkvl[ROWS * 3 * DD];
__device__ __align__(16) float         g_at[ROWS * DD];          // tf32, k-permuted
__device__ __align__(16) float         g_x2[ROWS * DD];
__device__ __align__(16) float         g_m[ROWS * DD];           // tf32, k-permuted
__device__ __align__(16) float         g_ff[ROWS * DFFN];        // tf32, k-permuted
__device__ __align__(16) __nv_bfloat16 g_wqkv_hi[3 * DD * DD], g_wqkv_lo[3 * DD * DD];
__device__ __align__(16) float         g_woT[DD * DD];           // k-permuted
__device__ __align__(16) float         g_wfcT[DFFN * DD];        // k-permuted
__device__ __align__(16) float         g_wprT[DD * DFFN];        // k-permuted

// ======================= portable PTX helpers ==============================
__device__ __forceinline__ uint32_t smem_u32(const void* p) {
    uint32_t a;
    asm("{ .reg .u64 t; cvta.to.shared.u64 t, %1; cvt.u32.u64 %0, t; }" : "=r"(a) : "l"(p));
    return a;
}

__device__ __forceinline__ void cp_async16(uint32_t saddr, const void* gaddr) {
    asm volatile("cp.async.cg.shared.global [%0], [%1], 16;" :: "r"(saddr), "l"(gaddr));
}
__device__ __forceinline__ void cp_commit() {
    asm volatile("cp.async.commit_group;" ::: "memory");
}
template <int N>
__device__ __forceinline__ void cp_wait() {
    asm volatile("cp.async.wait_group %0;" :: "n"(N) : "memory");
}

__device__ __forceinline__ void ldsm_x4(uint32_t* r, uint32_t addr) {
    asm volatile("ldmatrix.sync.aligned.m8n8.x4.shared.b16 {%0,%1,%2,%3}, [%4];"
        : "=r"(r[0]), "=r"(r[1]), "=r"(r[2]), "=r"(r[3]) : "r"(addr));
}
__device__ __forceinline__ void ldsm_x4_t(uint32_t* r, uint32_t addr) {
    asm volatile("ldmatrix.sync.aligned.m8n8.x4.trans.shared.b16 {%0,%1,%2,%3}, [%4];"
        : "=r"(r[0]), "=r"(r[1]), "=r"(r[2]), "=r"(r[3]) : "r"(addr));
}

__device__ __forceinline__ void mma16816(float* c, const uint32_t* a, const uint32_t* b) {
    asm volatile(
        "mma.sync.aligned.m16n8k16.row.col.f32.bf16.bf16.f32 "
        "{%0,%1,%2,%3}, {%4,%5,%6,%7}, {%8,%9}, {%0,%1,%2,%3};"
        : "+f"(c[0]), "+f"(c[1]), "+f"(c[2]), "+f"(c[3])
        : "r"(a[0]), "r"(a[1]), "r"(a[2]), "r"(a[3]), "r"(b[0]), "r"(b[1]));
}

__device__ __forceinline__ void mma_tf32(float* c, const uint32_t* a, const uint32_t* b) {
    asm volatile(
        "mma.sync.aligned.m16n8k8.row.col.f32.tf32.tf32.f32 "
        "{%0,%1,%2,%3}, {%4,%5,%6,%7}, {%8,%9}, {%0,%1,%2,%3};"
        : "+f"(c[0]), "+f"(c[1]), "+f"(c[2]), "+f"(c[3])
        : "r"(a[0]), "r"(a[1]), "r"(a[2]), "r"(a[3]), "r"(b[0]), "r"(b[1]));
}

__device__ __forceinline__ float to_tf32(float x) {
    uint32_t o;
    asm("cvt.rna.tf32.f32 %0, %1;" : "=r"(o) : "f"(x));
    return __uint_as_float(o);
}

// k-permutation within 8-groups: position 2t holds k=t, position 2t+1 holds k=t+4
__device__ __forceinline__ int pperm(int j) { return ((j & 3) << 1) | (j >> 2); }

// ======================= small math helpers ================================
// fast exp on the FMA pipe (no MUFU), clamped both ends
__device__ __forceinline__ float fexp(float x) {
    float y = fminf(fmaxf(x * 1.4426950408889634f, -126.0f), 126.0f);
    float z = y + 12582912.0f;
    int   n = __float_as_int(z) - 0x4B400000;
    float f = y - (z - 12582912.0f);
    float p = 0.0013333558146f;
    p = fmaf(p, f, 0.0096181291076f);
    p = fmaf(p, f, 0.0555041086648f);
    p = fmaf(p, f, 0.2402265069591f);
    p = fmaf(p, f, 0.6931471805599f);
    p = fmaf(p, f, 1.0f);
    return p * __int_as_float((n + 127) << 23);
}

// gelu (tanh approx) via exact identity: 0.5x(1+tanh z) = x / (1 + e^{-2z})
__device__ __forceinline__ float gelu_fast(float x) {
    float x2 = x * x;
    float z2 = 1.5957691216057308f * fmaf(0.044715f * x2, x, x);  // 2z
    float e = fexp(-z2);
    return __fdividef(x, 1.0f + e);
}

__device__ __forceinline__ void store_hilo4(__nv_bfloat16* oh, __nv_bfloat16* ol,
                                            size_t idx, float4 v)
{
    __nv_bfloat16 h0 = __float2bfloat16(v.x), h1 = __float2bfloat16(v.y);
    __nv_bfloat16 h2 = __float2bfloat16(v.z), h3 = __float2bfloat16(v.w);
    float l0 = v.x - __bfloat162float(h0), l1 = v.y - __bfloat162float(h1);
    float l2 = v.z - __bfloat162float(h2), l3 = v.w - __bfloat162float(h3);
    *(__nv_bfloat162*)(oh + idx)     = __halves2bfloat162(h0, h1);
    *(__nv_bfloat162*)(oh + idx + 2) = __halves2bfloat162(h2, h3);
    *(__nv_bfloat162*)(ol + idx)     = __halves2bfloat162(__float2bfloat16(l0), __float2bfloat16(l1));
    *(__nv_bfloat162*)(ol + idx + 2) = __halves2bfloat162(__float2bfloat16(l2), __float2bfloat16(l3));
}

__device__ __forceinline__ void store_hilo2(__nv_bfloat16* oh, __nv_bfloat16* ol,
                                            size_t idx, float a, float b)
{
    __nv_bfloat16 h0 = __float2bfloat16(a), h1 = __float2bfloat16(b);
    float l0 = a - __bfloat162float(h0), l1 = b - __bfloat162float(h1);
    *(__nv_bfloat162*)(oh + idx) = __halves2bfloat162(h0, h1);
    *(__nv_bfloat162*)(ol + idx) = __halves2bfloat162(__float2bfloat16(l0), __float2bfloat16(l1));
}

// ============ weight transpose + bf16 split (qkv only) =====================
__global__ void wsplit_t(const float* __restrict__ W, __nv_bfloat16* __restrict__ Th,
                         __nv_bfloat16* __restrict__ Tl, int K, int N)
{
    __shared__ float t[32][33];
    int bx = blockIdx.x, by = blockIdx.y;
    int x = threadIdx.x, y = threadIdx.y;
#pragma unroll
    for (int i = 0; i < 32; i += 8)
        t[y + i][x] = W[(size_t)(by * 32 + y + i) * N + bx * 32 + x];
    __syncthreads();
#pragma unroll
    for (int i = 0; i < 32; i += 8) {
        float v = t[x][y + i];
        __nv_bfloat16 h = __float2bfloat16(v);
        float lo = v - __bfloat162float(h);
        size_t o = (size_t)(bx * 32 + y + i) * K + by * 32 + x;
        Th[o] = h;
        Tl[o] = __float2bfloat16(lo);
    }
}

// ============ weight transpose + tf32 round, k-permuted (others) ===========
__global__ void wtrans(const float* __restrict__ W, float* __restrict__ T, int K, int N)
{
    __shared__ float t[32][33];
    int bx = blockIdx.x, by = blockIdx.y;
    int x = threadIdx.x, y = threadIdx.y;
#pragma unroll
    for (int i = 0; i < 32; i += 8)
        t[y + i][x] = W[(size_t)(by * 32 + y + i) * N + bx * 32 + x];
    __syncthreads();
    int kp = by * 32 + (x & ~7) + pperm(x & 7);   // permuted k index
#pragma unroll
    for (int i = 0; i < 32; i += 8)
        T[(size_t)(bx * 32 + y + i) * K + kp] = to_tf32(t[x][y + i]);
}

// ---------------- LayerNorm -> bf16 hi/lo (feeds bf16 GEMM) ----------------
__global__ void ln_bf(const float* __restrict__ x,
                      const float* __restrict__ gam,
                      const float* __restrict__ bet,
                      const float* __restrict__ pos,
                      __nv_bfloat16* __restrict__ oh,
                      __nv_bfloat16* __restrict__ ol)
{
    int row = blockIdx.x;
    int tid = threadIdx.x;
    const float4* xr = (const float4*)(x + (size_t)row * DD);
    float4 v = xr[tid];
    float s  = v.x + v.y + v.z + v.w;
    float ss = v.x * v.x + v.y * v.y + v.z * v.z + v.w * v.w;
#pragma unroll
    for (int o = 16; o > 0; o >>= 1) {
        s  += __shfl_xor_sync(0xffffffffu, s,  o);
        ss += __shfl_xor_sync(0xffffffffu, ss, o);
    }
    __shared__ float sb[8], sb2[8], stats[2];
    int wid = tid >> 5, lane = tid & 31;
    if (lane == 0) { sb[wid] = s; sb2[wid] = ss; }
    __syncthreads();
    if (tid == 0) {
        float ts = 0.f, tss = 0.f;
#pragma unroll
        for (int i = 0; i < 8; i++) { ts += sb[i]; tss += sb2[i]; }
        float mu  = ts  * (1.0f / DD);
        float var = tss * (1.0f / DD) - mu * mu;
        stats[0] = mu;
        stats[1] = rsqrtf(var + 1e-5f);
    }
    __syncthreads();
    float mu = stats[0], rs = stats[1];
    int c = tid * 4;
    float4 gg = *(const float4*)(gam + c);
    float4 bb = *(const float4*)(bet + c);
    float4 o4;
    o4.x = (v.x - mu) * rs * gg.x + bb.x;
    o4.y = (v.y - mu) * rs * gg.y + bb.y;
    o4.z = (v.z - mu) * rs * gg.z + bb.z;
    o4.w = (v.w - mu) * rs * gg.w + bb.w;
    if (pos) {
        int srow = row % SS;
        float4 p = *(const float4*)(pos + (size_t)srow * DD + c);
        o4.x += p.x; o4.y += p.y; o4.z += p.z; o4.w += p.w;
    }
    store_hilo4(oh, ol, (size_t)row * DD + c, o4);
}

// ---------------- LayerNorm -> tf32-rounded fp32, k-permuted ---------------
__global__ void ln_tf(const float* __restrict__ x,
                      const float* __restrict__ gam,
                      const float* __restrict__ bet,
                      float* __restrict__ out)
{
    int row = blockIdx.x;
    int tid = threadIdx.x;
    const float4* xr = (const float4*)(x + (size_t)row * DD);
    float4 v = xr[tid];
    float s  = v.x + v.y + v.z + v.w;
    float ss = v.x * v.x + v.y * v.y + v.z * v.z + v.w * v.w;
#pragma unroll
    for (int o = 16; o > 0; o >>= 1) {
        s  += __shfl_xor_sync(0xffffffffu, s,  o);
        ss += __shfl_xor_sync(0xffffffffu, ss, o);
    }
    __shared__ float sb[8], sb2[8], stats[2];
    int wid = tid >> 5, lane = tid & 31;
    if (lane == 0) { sb[wid] = s; sb2[wid] = ss; }
    __syncthreads();
    if (tid == 0) {
        float ts = 0.f, tss = 0.f;
#pragma unroll
        for (int i = 0; i < 8; i++) { ts += sb[i]; tss += sb2[i]; }
        float mu  = ts  * (1.0f / DD);
        float var = tss * (1.0f / DD) - mu * mu;
        stats[0] = mu;
        stats[1] = rsqrtf(var + 1e-5f);
    }
    __syncthreads();
    float mu = stats[0], rs = stats[1];
    int c = tid * 4;
    float4 gg = *(const float4*)(gam + c);
    float4 bb = *(const float4*)(bet + c);
    float vals[4];
    vals[0] = to_tf32((v.x - mu) * rs * gg.x + bb.x);
    vals[1] = to_tf32((v.y - mu) * rs * gg.y + bb.y);
    vals[2] = to_tf32((v.z - mu) * rs * gg.z + bb.z);
    vals[3] = to_tf32((v.w - mu) * rs * gg.w + bb.w);
    int base = c & ~7, o8 = c & 7;    // o8 = 0 or 4
    float* op = out + (size_t)row * DD + base;
#pragma unroll
    for (int i = 0; i < 4; i++)
        op[pperm(o8 + i)] = vals[i];
}

// =================== bf16 3-pass GEMM (qkv only; 3-stage pipeline) =========
#define OFF_AH 0
#define OFF_AL 8192
#define OFF_BH 16384
#define OFF_BL 24576
#define STAGE  32768
#define NSTAGE 3
#define TCG_SMEM (NSTAGE * STAGE)

__device__ __forceinline__ uint32_t swz32(int row, int chunk) {
    return (uint32_t)(row * 64 + (((chunk ^ (row >> 1)) & 3) << 4));
}

__device__ __forceinline__ void cp_stage(uint32_t sbase,
                                         const __nv_bfloat16* __restrict__ Ahi,
                                         const __nv_bfloat16* __restrict__ Alo,
                                         const __nv_bfloat16* __restrict__ Bhi,
                                         const __nv_bfloat16* __restrict__ Blo,
                                         int am0, int bn0, int k0, int ldk, int tid)
{
#pragma unroll
    for (int j = 0; j < 2; j++) {
        int v = tid + (j << 8);
        int r = v >> 2, c = v & 3;
        uint32_t so = swz32(r, c);
        size_t goA = (size_t)(am0 + r) * ldk + k0 + c * 8;
        size_t goB = (size_t)(bn0 + r) * ldk + k0 + c * 8;
        cp_async16(sbase + OFF_AH + so, Ahi + goA);
        cp_async16(sbase + OFF_AL + so, Alo + goA);
        cp_async16(sbase + OFF_BH + so, Bhi + goB);
        cp_async16(sbase + OFF_BL + so, Blo + goB);
    }
}

__global__ __launch_bounds__(256, 2)
void tc_gemm_bf(const __nv_bfloat16* __restrict__ Ahi, const __nv_bfloat16* __restrict__ Alo,
                const __nv_bfloat16* __restrict__ Bhi, const __nv_bfloat16* __restrict__ Blo,
                const float* __restrict__ bias,
                __nv_bfloat16* __restrict__ Chi, __nv_bfloat16* __restrict__ Clo,
                int M, int N, int K)
{
    extern __shared__ __align__(128) char smc[];
    uint32_t sb = smem_u32(smc);
    int tid = threadIdx.x, wid = tid >> 5, lane = tid & 31;
    int warp_m = wid >> 1, warp_n = wid & 1;
    int bn = blockIdx.x, bm = blockIdx.y;
    int am0 = bm * 128, bn0 = bn * 128;

    float acc[2][8][4];
#pragma unroll
    for (int mi = 0; mi < 2; mi++)
#pragma unroll
        for (int ni = 0; ni < 8; ni++)
#pragma unroll
            for (int q = 0; q < 4; q++) acc[mi][ni][q] = 0.f;

    int lrA = (lane & 7) + ((lane >> 3) & 1) * 8;
    uint32_t cAoff = (uint32_t)((lane >> 4) << 4);
    uint32_t aB[2], aX[2];
#pragma unroll
    for (int mi = 0; mi < 2; mi++) {
        int row = warp_m * 32 + mi * 16 + lrA;
        aB[mi] = (uint32_t)(row * 64);
        aX[mi] = cAoff ^ (uint32_t)((((row >> 1) & 3)) << 4);
    }
    int lrB = (lane & 7) + ((lane >> 4) & 1) * 8;
    uint32_t cBoff = (uint32_t)(((lane >> 3) & 1) << 4);
    uint32_t bB[4], bX[4];
#pragma unroll
    for (int p = 0; p < 4; p++) {
        int row = warp_n * 64 + p * 16 + lrB;
        bB[p] = (uint32_t)(row * 64);
        bX[p] = cBoff ^ (uint32_t)((((row >> 1) & 3)) << 4);
    }

    int nchunk = K >> 5;
    cp_stage(sb + 0 * STAGE, Ahi, Alo, Bhi, Blo, am0, bn0, 0, K, tid);
    cp_commit();
    cp_stage(sb + 1 * STAGE, Ahi, Alo, Bhi, Blo, am0, bn0, 32, K, tid);
    cp_commit();

    int slot = 0;
    for (int ch = 0; ch < nchunk; ch++) {
        uint32_t st = sb + (uint32_t)slot * STAGE;
        cp_wait<1>();
        __syncthreads();
        int nslot = slot + 2; if (nslot >= NSTAGE) nslot -= NSTAGE;
        if (ch + 2 < nchunk)
            cp_stage(sb + (uint32_t)nslot * STAGE, Ahi, Alo, Bhi, Blo,
                     am0, bn0, (ch + 2) << 5, K, tid);
        cp_commit();

#pragma unroll
        for (int ks = 0; ks < 2; ks++) {
            uint32_t kx = (uint32_t)(ks << 5);
            uint32_t ah[2][4], bh[8][2];
#pragma unroll
            for (int mi = 0; mi < 2; mi++)
                ldsm_x4(ah[mi], st + OFF_AH + aB[mi] + (kx ^ aX[mi]));
#pragma unroll
            for (int p = 0; p < 4; p++) {
                uint32_t r4[4];
                ldsm_x4(r4, st + OFF_BH + bB[p] + (kx ^ bX[p]));
                bh[2 * p][0] = r4[0]; bh[2 * p][1] = r4[1];
                bh[2 * p + 1][0] = r4[2]; bh[2 * p + 1][1] = r4[3];
            }
#pragma unroll
            for (int mi = 0; mi < 2; mi++)
#pragma unroll
                for (int ni = 0; ni < 8; ni++)
                    mma16816(acc[mi][ni], ah[mi], bh[ni]);
            {
                uint32_t al[2][4];
#pragma unroll
                for (int mi = 0; mi < 2; mi++)
                    ldsm_x4(al[mi], st + OFF_AL + aB[mi] + (kx ^ aX[mi]));
#pragma unroll
                for (int mi = 0; mi < 2; mi++)
#pragma unroll
                    for (int ni = 0; ni < 8; ni++)
                        mma16816(acc[mi][ni], al[mi], bh[ni]);
            }
            {
                uint32_t bl[8][2];
#pragma unroll
                for (int p = 0; p < 4; p++) {
                    uint32_t r4[4];
                    ldsm_x4(r4, st + OFF_BL + bB[p] + (kx ^ bX[p]));
                    bl[2 * p][0] = r4[0]; bl[2 * p][1] = r4[1];
                    bl[2 * p + 1][0] = r4[2]; bl[2 * p + 1][1] = r4[3];
                }
#pragma unroll
                for (int mi = 0; mi < 2; mi++)
#pragma unroll
                    for (int ni = 0; ni < 8; ni++)
                        mma16816(acc[mi][ni], ah[mi], bl[ni]);
            }
        }
        slot++; if (slot >= NSTAGE) slot = 0;
    }

    int g = lane >> 2, tig = lane & 3;
#pragma unroll
    for (int mi = 0; mi < 2; mi++) {
#pragma unroll
        for (int half = 0; half < 2; half++) {
            int r = bm * 128 + warp_m * 32 + mi * 16 + g + half * 8;
#pragma unroll
            for (int ni = 0; ni < 8; ni++) {
                int c = bn * 128 + warp_n * 64 + ni * 8 + tig * 2;
                float v0 = acc[mi][ni][half * 2 + 0];
                float v1 = acc[mi][ni][half * 2 + 1];
                float2 bv = *(const float2*)(bias + c);
                v0 += bv.x; v1 += bv.y;
                store_hilo2(Chi, Clo, (size_t)r * N + c, v0, v1);
            }
        }
    }
}

// ===== tf32 1-pass GEMM (k-permuted, XOR-swizzled rows, LDS.64 frags) ======
// Stage = two adjacent 16-k sub-tiles (identical proven layout each),
// 3 stages x 32 KB = 96 KB; barrier once per 32-k.
// 128x128 CTA, 256 thr (8 warps 2m x 4n, 64x32 warp tile).
// EPI: 1 = gelu(+bias) -> tf32 fp32 k-permuted ; 2 = +bias+res -> fp32
#define TTILEB 8192                 // bytes per 128x16 float tile
#define TSUB   (2 * TTILEB)         // 16 KB: A+B for one 16-k subchunk
#define TSTB   (2 * TSUB)           // 32 KB stage: two 16-k subchunks
#define TF_SMEM (3 * TSTB)          // 98304 bytes

__device__ __forceinline__ void cp_stage_tf(uint32_t sbase,
                                            const float* __restrict__ A,
                                            const float* __restrict__ Bt,
                                            int am0, int bn0, int k0, int ldk, int tid)
{
#pragma unroll
    for (int j = 0; j < 8; j++) {
        int idx = tid + (j << 8);        // 0..2047
        int sub = idx >> 10;             // which 16-k subchunk
        int w = idx & 1023;
        int tile = w >> 9;               // 0 = A, 1 = B
        int v = w & 511;
        int r = v >> 2, c = v & 3;       // row, 16B chunk
        uint32_t dst = sbase + (uint32_t)sub * TSUB + (uint32_t)tile * TTILEB
                     + (uint32_t)(r * 64) + (uint32_t)(((c ^ (r & 3)) << 4));
        const float* src = (tile ? Bt + (size_t)(bn0 + r) * ldk : A + (size_t)(am0 + r) * ldk)
                           + k0 + sub * 16 + c * 4;
        cp_async16(dst, src);
    }
}

template <int EPI>
__global__ __launch_bounds__(256, 2)
void tf_gemm(const float* __restrict__ A, const float* __restrict__ Bt,
             const float* __restrict__ bias, const float* __restrict__ res,
             float* __restrict__ Cf, int M, int N, int K)
{
    extern __shared__ __align__(128) float smf[];
    int tid = threadIdx.x, wid = tid >> 5, lane = tid & 31;
    int warp_m = wid >> 2, warp_n = wid & 3;     // 2m x 4n
    int g = lane >> 2, tig = lane & 3;
    int bn = blockIdx.x, bm = blockIdx.y;
    int am0 = bm * 128, bn0 = bn * 128;

    float acc[4][4][4];
#pragma unroll
    for (int mi = 0; mi < 4; mi++)
#pragma unroll
        for (int ni = 0; ni < 4; ni++)
#pragma unroll
            for (int q = 0; q < 4; q++) acc[mi][ni][q] = 0.f;

    int nchunk = K >> 5;                 // 32-k chunks
    uint32_t sb = smem_u32(smf);
    cp_stage_tf(sb + 0 * TSTB, A, Bt, am0, bn0, 0, K, tid);
    cp_commit();
    cp_stage_tf(sb + 1 * TSTB, A, Bt, am0, bn0, 32, K, tid);
    cp_commit();

    int subo = (tig & 1) * 2;
    int cjt  = tig >> 1;

    int slot = 0;
    for (int ch = 0; ch < nchunk; ch++) {
        cp_wait<1>();
        __syncthreads();
        int nslot = slot + 2; if (nslot >= 3) nslot -= 3;
        if (ch + 2 < nchunk)
            cp_stage_tf(sb + (uint32_t)nslot * TSTB, A, Bt, am0, bn0,
                        (ch + 2) << 5, K, tid);
        cp_commit();

#pragma unroll
        for (int sub = 0; sub < 2; sub++) {
            const float* As = smf + slot * (TSTB / 4) + sub * (TSUB / 4);
            const float* Bs = As + (TTILEB / 4);

#pragma unroll
            for (int ks = 0; ks < 2; ks++) {
                int cj = ks * 2 + cjt;
                uint32_t a[4][4];
#pragma unroll
                for (int mi = 0; mi < 4; mi++) {
                    int r0 = warp_m * 64 + mi * 16 + g;
                    int r1 = r0 + 8;
                    float2 f0 = *(const float2*)&As[r0 * 16 + ((cj ^ (r0 & 3)) << 2) + subo];
                    float2 f1 = *(const float2*)&As[r1 * 16 + ((cj ^ (r1 & 3)) << 2) + subo];
                    a[mi][0] = __float_as_uint(f0.x);
                    a[mi][1] = __float_as_uint(f1.x);
                    a[mi][2] = __float_as_uint(f0.y);
                    a[mi][3] = __float_as_uint(f1.y);
                }
                uint32_t b[4][2];
#pragma unroll
                for (int ni = 0; ni < 4; ni++) {
                    int rn = warp_n * 32 + ni * 8 + g;
                    float2 f = *(const float2*)&Bs[rn * 16 + ((cj ^ (rn & 3)) << 2) + subo];
                    b[ni][0] = __float_as_uint(f.x);
                    b[ni][1] = __float_as_uint(f.y);
                }
#pragma unroll
                for (int mi = 0; mi < 4; mi++)
#pragma unroll
                    for (int ni = 0; ni < 4; ni++)
                        mma_tf32(acc[mi][ni], a[mi], b[ni]);
            }
        }
        slot++; if (slot >= 3) slot = 0;
    }

#pragma unroll
    for (int mi = 0; mi < 4; mi++) {
#pragma unroll
        for (int half = 0; half < 2; half++) {
            int r = bm * 128 + warp_m * 64 + mi * 16 + g + half * 8;
#pragma unroll
            for (int ni = 0; ni < 4; ni++) {
                int c = bn * 128 + warp_n * 32 + ni * 8 + tig * 2;
                float v0 = acc[mi][ni][half * 2 + 0];
                float v1 = acc[mi][ni][half * 2 + 1];
                float2 bv = *(const float2*)(bias + c);
                v0 += bv.x; v1 += bv.y;
                size_t rowb = (size_t)r * N;
                if (EPI == 1) {
                    int cb = c & ~7, j = c & 7;
                    Cf[rowb + cb + pperm(j)]     = to_tf32(gelu_fast(v0));
                    Cf[rowb + cb + pperm(j + 1)] = to_tf32(gelu_fast(v1));
                } else {
                    float2 rv = *(const float2*)(res + rowb + c);
                    v0 += rv.x; v1 += rv.y;
                    *(float2*)(Cf + rowb + c) = make_float2(v0, v1);
                }
            }
        }
    }
}

// ============ Tensor-core causal flash attention (cp.async pipelined) ======
#define AQH 0
#define AQL 8192
#define ASTG 16384
#define SKH 0
#define SKL 8192
#define SVH 16384
#define SVL 24576
#define SSTG 32768
#define ATT_SMEM (ASTG + 3 * SSTG)   // 112 KB

__device__ __forceinline__ void attn_cp_kv(uint32_t stg,
                                           const __nv_bfloat16* __restrict__ qh,
                                           const __nv_bfloat16* __restrict__ ql,
                                           size_t rowbase, int hoff, int tid)
{
#pragma unroll
    for (int j = 0; j < 4; j++) {
        int idx = tid + (j << 7);
        int r = idx >> 3, c = idx & 7;
        uint32_t ad = (uint32_t)(r * 128) + (uint32_t)(((c ^ r) & 7) << 4);
        size_t gK = rowbase + (size_t)r * (3 * DD) + DD + hoff + c * 8;
        size_t gV = rowbase + (size_t)r * (3 * DD) + 2 * DD + hoff + c * 8;
        cp_async16(stg + SKH + ad, qh + gK);
        cp_async16(stg + SKL + ad, ql + gK);
        cp_async16(stg + SVH + ad, qh + gV);
        cp_async16(stg + SVL + ad, ql + gV);
    }
}

__global__ __launch_bounds__(128)
void attn_kernel(const __nv_bfloat16* __restrict__ qkvh,
                 const __nv_bfloat16* __restrict__ qkvl,
                 float* __restrict__ oat)
{
    extern __shared__ __align__(128) char sma[];
    uint32_t sb = smem_u32(sma);
    int qt = (int)gridDim.x - 1 - (int)blockIdx.x;
    int h = blockIdx.y, b = blockIdx.z;
    int tid = threadIdx.x, warp = tid >> 5, lane = tid & 31;
    int q0 = qt * 64;
    int g = lane >> 2, tig = lane & 3;
    int hoff = h * HDIM;

    {
        size_t rowQ = (size_t)(b * SS + q0) * (3 * DD);
#pragma unroll
        for (int j = 0; j < 4; j++) {
            int idx = tid + (j << 7);
            int r = idx >> 3, c = idx & 7;
            uint32_t ad = (uint32_t)(r * 128) + (uint32_t)(((c ^ r) & 7) << 4);
            size_t gQ = rowQ + (size_t)r * (3 * DD) + hoff + c * 8;
            cp_async16(sb + AQH + ad, qkvh + gQ);
            cp_async16(sb + AQL + ad, qkvl + gQ);
        }
        attn_cp_kv(sb + ASTG, qkvh, qkvl, (size_t)(b * SS) * (3 * DD), hoff, tid);
        cp_commit();
        attn_cp_kv(sb + ASTG + SSTG, qkvh, qkvl,
                   (size_t)(b * SS + 64) * (3 * DD), hoff, tid);
        cp_commit();
    }

    int lrA = (lane & 7) + ((lane >> 3) & 1) * 8;
    uint32_t cA = (uint32_t)((lane >> 4) << 4);
    int rowA = warp * 16 + lrA;
    uint32_t aBase = (uint32_t)(rowA * 128);
    uint32_t aMask = (uint32_t)((rowA & 7) << 4);

    int lrB = (lane & 7) + ((lane >> 4) & 1) * 8;
    uint32_t cB = (uint32_t)(((lane >> 3) & 1) << 4);

    int lrV = (lane & 7) + ((lane >> 3) & 1) * 8;
    uint32_t cV = (uint32_t)(((lane >> 4) & 1) << 4);

    float oacc[8][4];
    float mA = -1e30f, mB = -1e30f, lA = 0.f, lB = 0.f;
#pragma unroll
    for (int t = 0; t < 8; t++)
#pragma unroll
        for (int q = 0; q < 4; q++) oacc[t][q] = 0.f;

    int slot = 0;
    for (int kt = 0; kt <= qt; kt++) {
        uint32_t st = sb + ASTG + (uint32_t)slot * SSTG;
        cp_wait<1>();
        __syncthreads();
        int nslot = slot + 2; if (nslot >= 3) nslot -= 3;
        if (kt + 2 <= qt)
            attn_cp_kv(sb + ASTG + (uint32_t)nslot * SSTG, qkvh, qkvl,
                       (size_t)(b * SS + (kt + 2) * 64) * (3 * DD), hoff, tid);
        cp_commit();

        float sacc[8][4];
#pragma unroll
        for (int t = 0; t < 8; t++)
#pragma unroll
            for (int q = 0; q < 4; q++) sacc[t][q] = 0.f;

#pragma unroll
        for (int ks = 0; ks < 4; ks++) {
            uint32_t kx = (uint32_t)(ks * 32);
            uint32_t qh4[4], ql4[4], kh[8][2];
            ldsm_x4(qh4, sb + AQH + aBase + ((kx + cA) ^ aMask));
            ldsm_x4(ql4, sb + AQL + aBase + ((kx + cA) ^ aMask));
#pragma unroll
            for (int p = 0; p < 4; p++) {
                int rowB = p * 16 + lrB;
                uint32_t r4[4];
                ldsm_x4(r4, st + SKH + (uint32_t)(rowB * 128) +
                            ((kx + cB) ^ (uint32_t)((rowB & 7) << 4)));
                kh[2 * p][0] = r4[0]; kh[2 * p][1] = r4[1];
                kh[2 * p + 1][0] = r4[2]; kh[2 * p + 1][1] = r4[3];
            }
#pragma unroll
            for (int t = 0; t < 8; t++) mma16816(sacc[t], qh4, kh[t]);
#pragma unroll
            for (int t = 0; t < 8; t++) mma16816(sacc[t], ql4, kh[t]);
            {
                uint32_t kl[8][2];
#pragma unroll
                for (int p = 0; p < 4; p++) {
                    int rowB = p * 16 + lrB;
                    uint32_t r4[4];
                    ldsm_x4(r4, st + SKL + (uint32_t)(rowB * 128) +
                                ((kx + cB) ^ (uint32_t)((rowB & 7) << 4)));
                    kl[2 * p][0] = r4[0]; kl[2 * p][1] = r4[1];
                    kl[2 * p + 1][0] = r4[2]; kl[2 * p + 1][1] = r4[3];
                }
#pragma unroll
                for (int t = 0; t < 8; t++) mma16816(sacc[t], qh4, kl[t]);
            }
        }

#pragma unroll
        for (int t = 0; t < 8; t++) {
            sacc[t][0] *= 0.125f; sacc[t][1] *= 0.125f;
            sacc[t][2] *= 0.125f; sacc[t][3] *= 0.125f;
        }

        if (kt == qt) {
            int qlocA = warp * 16 + g, qlocB = qlocA + 8;
#pragma unroll
            for (int t = 0; t < 8; t++) {
                int k0c = t * 8 + tig * 2;
                if (k0c > qlocA)     sacc[t][0] = -1e30f;
                if (k0c + 1 > qlocA) sacc[t][1] = -1e30f;
                if (k0c > qlocB)     sacc[t][2] = -1e30f;
                if (k0c + 1 > qlocB) sacc[t][3] = -1e30f;
            }
        }

        float maA = -1e30f, maB = -1e30f;
#pragma unroll
        for (int t = 0; t < 8; t++) {
            maA = fmaxf(maA, fmaxf(sacc[t][0], sacc[t][1]));
            maB = fmaxf(maB, fmaxf(sacc[t][2], sacc[t][3]));
        }
        maA = fmaxf(maA, __shfl_xor_sync(0xffffffffu, maA, 1));
        maA = fmaxf(maA, __shfl_xor_sync(0xffffffffu, maA, 2));
        maB = fmaxf(maB, __shfl_xor_sync(0xffffffffu, maB, 1));
        maB = fmaxf(maB, __shfl_xor_sync(0xffffffffu, maB, 2));
        float nmA = fmaxf(mA, maA), nmB = fmaxf(mB, maB);
        float corrA = fexp(mA - nmA), corrB = fexp(mB - nmB);
        mA = nmA; mB = nmB;
        float sumA = 0.f, sumB = 0.f;
#pragma unroll
        for (int t = 0; t < 8; t++) {
            sacc[t][0] = fexp(sacc[t][0] - nmA);
            sacc[t][1] = fexp(sacc[t][1] - nmA);
            sacc[t][2] = fexp(sacc[t][2] - nmB);
            sacc[t][3] = fexp(sacc[t][3] - nmB);
            sumA += sacc[t][0] + sacc[t][1];
            sumB += sacc[t][2] + sacc[t][3];
        }
        sumA += __shfl_xor_sync(0xffffffffu, sumA, 1);
        sumA += __shfl_xor_sync(0xffffffffu, sumA, 2);
        sumB += __shfl_xor_sync(0xffffffffu, sumB, 1);
        sumB += __shfl_xor_sync(0xffffffffu, sumB, 2);
        lA = lA * corrA + sumA;
        lB = lB * corrB + sumB;
#pragma unroll
        for (int t = 0; t < 8; t++) {
            oacc[t][0] *= corrA; oacc[t][1] *= corrA;
            oacc[t][2] *= corrB; oacc[t][3] *= corrB;
        }

        uint32_t ph[4][4], pl[4][4];
#pragma unroll
        for (int p = 0; p < 4; p++) {
#pragma unroll
            for (int q = 0; q < 4; q++) {
                int t = 2 * p + (q >> 1);
                float a = sacc[t][(q & 1) * 2 + 0];
                float bv = sacc[t][(q & 1) * 2 + 1];
                __nv_bfloat16 ah2 = __float2bfloat16(a), bh2 = __float2bfloat16(bv);
                __nv_bfloat162 th = __halves2bfloat162(ah2, bh2);
                ph[p][q] = *(uint32_t*)&th;
                __nv_bfloat162 tl = __halves2bfloat162(
                    __float2bfloat16(a - __bfloat162float(ah2)),
                    __float2bfloat16(bv - __bfloat162float(bh2)));
                pl[p][q] = *(uint32_t*)&tl;
            }
        }

#pragma unroll
        for (int ks = 0; ks < 4; ks++) {
            int rowV = ks * 16 + lrV;
            uint32_t vMask = (uint32_t)((rowV & 7) << 4);
            uint32_t vbh[8][2], vbl[8][2];
#pragma unroll
            for (int j = 0; j < 4; j++) {
                uint32_t cb = (uint32_t)(j * 32) + cV;
                uint32_t r4[4];
                ldsm_x4_t(r4, st + SVH + (uint32_t)(rowV * 128) + (cb ^ vMask));
                vbh[2 * j][0] = r4[0]; vbh[2 * j][1] = r4[1];
                vbh[2 * j + 1][0] = r4[2]; vbh[2 * j + 1][1] = r4[3];
            }
#pragma unroll
            for (int j = 0; j < 4; j++) {
                uint32_t cb = (uint32_t)(j * 32) + cV;
                uint32_t r4[4];
                ldsm_x4_t(r4, st + SVL + (uint32_t)(rowV * 128) + (cb ^ vMask));
                vbl[2 * j][0] = r4[0]; vbl[2 * j][1] = r4[1];
                vbl[2 * j + 1][0] = r4[2]; vbl[2 * j + 1][1] = r4[3];
            }
#pragma unroll
            for (int t = 0; t < 8; t++) mma16816(oacc[t], ph[ks], vbh[t]);
#pragma unroll
            for (int t = 0; t < 8; t++) mma16816(oacc[t], pl[ks], vbh[t]);
#pragma unroll
            for (int t = 0; t < 8; t++) mma16816(oacc[t], ph[ks], vbl[t]);
        }
        slot++; if (slot >= 3) slot = 0;
    }

    // ---- normalize + k-permuted write (feeds o-proj tf32 GEMM) ----
    float invA = 1.0f / lA, invB = 1.0f / lB;
    int rowAg = b * SS + q0 + warp * 16 + g;
    int rowBg = rowAg + 8;
#pragma unroll
    for (int t = 0; t < 8; t++) {
        int gbase = h * HDIM + t * 8;
        int j0 = tig * 2;
        float* pA = oat + (size_t)rowAg * DD + gbase;
        float* pB = oat + (size_t)rowBg * DD + gbase;
        pA[pperm(j0)]     = to_tf32(oacc[t][0] * invA);
        pA[pperm(j0 + 1)] = to_tf32(oacc[t][1] * invA);
        pB[pperm(j0)]     = to_tf32(oacc[t][2] * invB);
        pB[pperm(j0 + 1)] = to_tf32(oacc[t][3] * invB);
    }
}

// ---------------- launch ---------------------------------------------------
extern "C" void kernel_launch(void* const* d_in, const int* in_sizes, int n_in,
                              void* d_out, int out_size)
{
    const float* x    = (const float*)d_in[0];
    const float* pos  = (const float*)d_in[1];
    const float* ln1g = (const float*)d_in[2];
    const float* ln1b = (const float*)d_in[3];
    const float* wqkv = (const float*)d_in[4];
    const float* bqkv = (const float*)d_in[5];
    const float* wo   = (const float*)d_in[6];
    const float* bo   = (const float*)d_in[7];
    const float* ln2g = (const float*)d_in[8];
    const float* ln2b = (const float*)d_in[9];
    const float* wfc  = (const float*)d_in[10];
    const float* bfc  = (const float*)d_in[11];
    const float* wpr  = (const float*)d_in[12];
    const float* bpr  = (const float*)d_in[13];
    float* out = (float*)d_out;

    __nv_bfloat16 *p_h_hi, *p_h_lo, *p_qkvh, *p_qkvl, *p_wqkv_hi, *p_wqkv_lo;
    float *p_at, *p_x2, *p_m, *p_ff, *p_woT, *p_wfcT, *p_wprT;
    cudaGetSymbolAddress((void**)&p_h_hi, g_h_hi);   cudaGetSymbolAddress((void**)&p_h_lo, g_h_lo);
    cudaGetSymbolAddress((void**)&p_qkvh, g_qkvh);   cudaGetSymbolAddress((void**)&p_qkvl, g_qkvl);
    cudaGetSymbolAddress((void**)&p_at, g_at);
    cudaGetSymbolAddress((void**)&p_x2, g_x2);
    cudaGetSymbolAddress((void**)&p_m, g_m);
    cudaGetSymbolAddress((void**)&p_ff, g_ff);
    cudaGetSymbolAddress((void**)&p_wqkv_hi, g_wqkv_hi); cudaGetSymbolAddress((void**)&p_wqkv_lo, g_wqkv_lo);
    cudaGetSymbolAddress((void**)&p_woT, g_woT);
    cudaGetSymbolAddress((void**)&p_wfcT, g_wfcT);
    cudaGetSymbolAddress((void**)&p_wprT, g_wprT);

    cudaFuncSetAttribute(tc_gemm_bf, cudaFuncAttributeMaxDynamicSharedMemorySize, TCG_SMEM);
    cudaFuncSetAttribute(tf_gemm<1>, cudaFuncAttributeMaxDynamicSharedMemorySize, TF_SMEM);
    cudaFuncSetAttribute(tf_gemm<2>, cudaFuncAttributeMaxDynamicSharedMemorySize, TF_SMEM);
    cudaFuncSetAttribute(attn_kernel, cudaFuncAttributeMaxDynamicSharedMemorySize, ATT_SMEM);

    dim3 tb(32, 8);
    wsplit_t<<<dim3(3 * DD / 32, DD / 32), tb>>>(wqkv, p_wqkv_hi, p_wqkv_lo, DD, 3 * DD);
    wtrans<<<dim3(DD / 32, DD / 32), tb>>>(wo, p_woT, DD, DD);
    wtrans<<<dim3(DFFN / 32, DD / 32), tb>>>(wfc, p_wfcT, DD, DFFN);
    wtrans<<<dim3(DD / 32, DFFN / 32), tb>>>(wpr, p_wprT, DFFN, DD);

    // 1) h = LN1(x) + pos -> bf16 hi/lo
    ln_bf<<<ROWS, 256>>>(x, ln1g, ln1b, pos, p_h_hi, p_h_lo);

    // 2) qkv = h @ w_qkv + b_qkv -> bf16 hi/lo (3-pass, accuracy-critical)
    tc_gemm_bf<<<dim3(3 * DD / 128, ROWS / 128), 256, TCG_SMEM>>>(
        p_h_hi, p_h_lo, p_wqkv_hi, p_wqkv_lo, bqkv,
        p_qkvh, p_qkvl, ROWS, 3 * DD, DD);

    // 3) causal attention -> tf32 fp32, k-permuted
    attn_kernel<<<dim3(SS / 64, HH, BB), 128, ATT_SMEM>>>(p_qkvh, p_qkvl, p_at);

    // 4) x2 = x + attn @ w_o + b_o (tf32)
    tf_gemm<2><<<dim3(DD / 128, ROWS / 128), 256, TF_SMEM>>>(
        p_at, p_woT, bo, x, p_x2, ROWS, DD, DD);

    // 5) m = LN2(x2) -> tf32 fp32, k-permuted
    ln_tf<<<ROWS, 256>>>(p_x2, ln2g, ln2b, p_m);

    // 6) ff = gelu(m @ w_fc + b_fc) (tf32) -> tf32 fp32, k-permuted
    tf_gemm<1><<<dim3(DFFN / 128, ROWS / 128), 256, TF_SMEM>>>(
        p_m, p_wfcT, bfc, nullptr, p_ff, ROWS, DFFN, DD);

    // 7) out = x2 + ff @ w_proj + b_proj (tf32)
    tf_gemm<2><<<dim3(DD / 128, ROWS / 128), 256, TF_SMEM>>>(
        p_ff, p_wprT, bpr, p_x2, out, ROWS, DD, DFFN);
}

// round 14
// speedup vs baseline: 1.0255x; 1.0255x over previous
#include <cuda_runtime.h>
#include <cuda_bf16.h>
#include <math.h>
#include <stdint.h>

// Problem constants
#define BB   2
#define SS   2048
#define DD   1024
#define HH   16
#define HDIM 64
#define DFFN 4096
#define ROWS (BB * SS)   // 4096

// -------- scratch (static device globals; no allocation) --------
__device__ __align__(16) __nv_bfloat16 g_h_hi[ROWS * DD], g_h_lo[ROWS * DD];
__device__ __align__(16) __nv_bfloat16 g_qkvh[ROWS * 3 * DD], g_qkvl[ROWS * 3 * DD];
__device__ __align__(16) float         g_at[ROWS * DD];          // tf32, k-permuted
__device__ __align__(16) float         g_x2[ROWS * DD];
__device__ __align__(16) float         g_m[ROWS * DD];           // tf32, k-permuted
__device__ __align__(16) float         g_ff[ROWS * DFFN];        // tf32, k-permuted
__device__ __align__(16) __nv_bfloat16 g_wqkv_hi[3 * DD * DD], g_wqkv_lo[3 * DD * DD];
__device__ __align__(16) float         g_woT[DD * DD];           // k-permuted
__device__ __align__(16) float         g_wfcT[DFFN * DD];        // k-permuted
__device__ __align__(16) float         g_wprT[DD * DFFN];        // k-permuted

// ======================= portable PTX helpers ==============================
__device__ __forceinline__ uint32_t smem_u32(const void* p) {
    uint32_t a;
    asm("{ .reg .u64 t; cvta.to.shared.u64 t, %1; cvt.u32.u64 %0, t; }" : "=r"(a) : "l"(p));
    return a;
}

__device__ __forceinline__ void cp_async16(uint32_t saddr, const void* gaddr) {
    asm volatile("cp.async.cg.shared.global [%0], [%1], 16;" :: "r"(saddr), "l"(gaddr));
}
__device__ __forceinline__ void cp_commit() {
    asm volatile("cp.async.commit_group;" ::: "memory");
}
template <int N>
__device__ __forceinline__ void cp_wait() {
    asm volatile("cp.async.wait_group %0;" :: "n"(N) : "memory");
}

__device__ __forceinline__ void ldsm_x4(uint32_t* r, uint32_t addr) {
    asm volatile("ldmatrix.sync.aligned.m8n8.x4.shared.b16 {%0,%1,%2,%3}, [%4];"
        : "=r"(r[0]), "=r"(r[1]), "=r"(r[2]), "=r"(r[3]) : "r"(addr));
}
__device__ __forceinline__ void ldsm_x4_t(uint32_t* r, uint32_t addr) {
    asm volatile("ldmatrix.sync.aligned.m8n8.x4.trans.shared.b16 {%0,%1,%2,%3}, [%4];"
        : "=r"(r[0]), "=r"(r[1]), "=r"(r[2]), "=r"(r[3]) : "r"(addr));
}

__device__ __forceinline__ void mma16816(float* c, const uint32_t* a, const uint32_t* b) {
    asm volatile(
        "mma.sync.aligned.m16n8k16.row.col.f32.bf16.bf16.f32 "
        "{%0,%1,%2,%3}, {%4,%5,%6,%7}, {%8,%9}, {%0,%1,%2,%3};"
        : "+f"(c[0]), "+f"(c[1]), "+f"(c[2]), "+f"(c[3])
        : "r"(a[0]), "r"(a[1]), "r"(a[2]), "r"(a[3]), "r"(b[0]), "r"(b[1]));
}

__device__ __forceinline__ void mma_tf32(float* c, const uint32_t* a, const uint32_t* b) {
    asm volatile(
        "mma.sync.aligned.m16n8k8.row.col.f32.tf32.tf32.f32 "
        "{%0,%1,%2,%3}, {%4,%5,%6,%7}, {%8,%9}, {%0,%1,%2,%3};"
        : "+f"(c[0]), "+f"(c[1]), "+f"(c[2]), "+f"(c[3])
        : "r"(a[0]), "r"(a[1]), "r"(a[2]), "r"(a[3]), "r"(b[0]), "r"(b[1]));
}

__device__ __forceinline__ float to_tf32(float x) {
    uint32_t o;
    asm("cvt.rna.tf32.f32 %0, %1;" : "=r"(o) : "f"(x));
    return __uint_as_float(o);
}

// k-permutation within 8-groups: position 2t holds k=t, position 2t+1 holds k=t+4
__device__ __forceinline__ int pperm(int j) { return ((j & 3) << 1) | (j >> 2); }

// ======================= small math helpers ================================
// fast exp on the FMA pipe (no MUFU), clamped both ends
__device__ __forceinline__ float fexp(float x) {
    float y = fminf(fmaxf(x * 1.4426950408889634f, -126.0f), 126.0f);
    float z = y + 12582912.0f;
    int   n = __float_as_int(z) - 0x4B400000;
    float f = y - (z - 12582912.0f);
    float p = 0.0013333558146f;
    p = fmaf(p, f, 0.0096181291076f);
    p = fmaf(p, f, 0.0555041086648f);
    p = fmaf(p, f, 0.2402265069591f);
    p = fmaf(p, f, 0.6931471805599f);
    p = fmaf(p, f, 1.0f);
    return p * __int_as_float((n + 127) << 23);
}

// gelu (tanh approx) via exact identity: 0.5x(1+tanh z) = x / (1 + e^{-2z})
__device__ __forceinline__ float gelu_fast(float x) {
    float x2 = x * x;
    float z2 = 1.5957691216057308f * fmaf(0.044715f * x2, x, x);  // 2z
    float e = fexp(-z2);
    return __fdividef(x, 1.0f + e);
}

__device__ __forceinline__ void store_hilo4(__nv_bfloat16* oh, __nv_bfloat16* ol,
                                            size_t idx, float4 v)
{
    __nv_bfloat16 h0 = __float2bfloat16(v.x), h1 = __float2bfloat16(v.y);
    __nv_bfloat16 h2 = __float2bfloat16(v.z), h3 = __float2bfloat16(v.w);
    float l0 = v.x - __bfloat162float(h0), l1 = v.y - __bfloat162float(h1);
    float l2 = v.z - __bfloat162float(h2), l3 = v.w - __bfloat162float(h3);
    *(__nv_bfloat162*)(oh + idx)     = __halves2bfloat162(h0, h1);
    *(__nv_bfloat162*)(oh + idx + 2) = __halves2bfloat162(h2, h3);
    *(__nv_bfloat162*)(ol + idx)     = __halves2bfloat162(__float2bfloat16(l0), __float2bfloat16(l1));
    *(__nv_bfloat162*)(ol + idx + 2) = __halves2bfloat162(__float2bfloat16(l2), __float2bfloat16(l3));
}

__device__ __forceinline__ void store_hilo2(__nv_bfloat16* oh, __nv_bfloat16* ol,
                                            size_t idx, float a, float b)
{
    __nv_bfloat16 h0 = __float2bfloat16(a), h1 = __float2bfloat16(b);
    float l0 = a - __bfloat162float(h0), l1 = b - __bfloat162float(h1);
    *(__nv_bfloat162*)(oh + idx) = __halves2bfloat162(h0, h1);
    *(__nv_bfloat162*)(ol + idx) = __halves2bfloat162(__float2bfloat16(l0), __float2bfloat16(l1));
}

// ============ weight transpose + bf16 split (qkv only) =====================
__global__ void wsplit_t(const float* __restrict__ W, __nv_bfloat16* __restrict__ Th,
                         __nv_bfloat16* __restrict__ Tl, int K, int N)
{
    __shared__ float t[32][33];
    int bx = blockIdx.x, by = blockIdx.y;
    int x = threadIdx.x, y = threadIdx.y;
#pragma unroll
    for (int i = 0; i < 32; i += 8)
        t[y + i][x] = W[(size_t)(by * 32 + y + i) * N + bx * 32 + x];
    __syncthreads();
#pragma unroll
    for (int i = 0; i < 32; i += 8) {
        float v = t[x][y + i];
        __nv_bfloat16 h = __float2bfloat16(v);
        float lo = v - __bfloat162float(h);
        size_t o = (size_t)(bx * 32 + y + i) * K + by * 32 + x;
        Th[o] = h;
        Tl[o] = __float2bfloat16(lo);
    }
}

// ============ weight transpose + tf32 round, k-permuted (others) ===========
__global__ void wtrans(const float* __restrict__ W, float* __restrict__ T, int K, int N)
{
    __shared__ float t[32][33];
    int bx = blockIdx.x, by = blockIdx.y;
    int x = threadIdx.x, y = threadIdx.y;
#pragma unroll
    for (int i = 0; i < 32; i += 8)
        t[y + i][x] = W[(size_t)(by * 32 + y + i) * N + bx * 32 + x];
    __syncthreads();
    int kp = by * 32 + (x & ~7) + pperm(x & 7);   // permuted k index
#pragma unroll
    for (int i = 0; i < 32; i += 8)
        T[(size_t)(bx * 32 + y + i) * K + kp] = to_tf32(t[x][y + i]);
}

// ---------------- LayerNorm -> bf16 hi/lo (feeds bf16 GEMM) ----------------
__global__ void ln_bf(const float* __restrict__ x,
                      const float* __restrict__ gam,
                      const float* __restrict__ bet,
                      const float* __restrict__ pos,
                      __nv_bfloat16* __restrict__ oh,
                      __nv_bfloat16* __restrict__ ol)
{
    int row = blockIdx.x;
    int tid = threadIdx.x;
    const float4* xr = (const float4*)(x + (size_t)row * DD);
    float4 v = xr[tid];
    float s  = v.x + v.y + v.z + v.w;
    float ss = v.x * v.x + v.y * v.y + v.z * v.z + v.w * v.w;
#pragma unroll
    for (int o = 16; o > 0; o >>= 1) {
        s  += __shfl_xor_sync(0xffffffffu, s,  o);
        ss += __shfl_xor_sync(0xffffffffu, ss, o);
    }
    __shared__ float sb[8], sb2[8], stats[2];
    int wid = tid >> 5, lane = tid & 31;
    if (lane == 0) { sb[wid] = s; sb2[wid] = ss; }
    __syncthreads();
    if (tid == 0) {
        float ts = 0.f, tss = 0.f;
#pragma unroll
        for (int i = 0; i < 8; i++) { ts += sb[i]; tss += sb2[i]; }
        float mu  = ts  * (1.0f / DD);
        float var = tss * (1.0f / DD) - mu * mu;
        stats[0] = mu;
        stats[1] = rsqrtf(var + 1e-5f);
    }
    __syncthreads();
    float mu = stats[0], rs = stats[1];
    int c = tid * 4;
    float4 gg = *(const float4*)(gam + c);
    float4 bb = *(const float4*)(bet + c);
    float4 o4;
    o4.x = (v.x - mu) * rs * gg.x + bb.x;
    o4.y = (v.y - mu) * rs * gg.y + bb.y;
    o4.z = (v.z - mu) * rs * gg.z + bb.z;
    o4.w = (v.w - mu) * rs * gg.w + bb.w;
    if (pos) {
        int srow = row % SS;
        float4 p = *(const float4*)(pos + (size_t)srow * DD + c);
        o4.x += p.x; o4.y += p.y; o4.z += p.z; o4.w += p.w;
    }
    store_hilo4(oh, ol, (size_t)row * DD + c, o4);
}

// ---------------- LayerNorm -> tf32-rounded fp32, k-permuted ---------------
__global__ void ln_tf(const float* __restrict__ x,
                      const float* __restrict__ gam,
                      const float* __restrict__ bet,
                      float* __restrict__ out)
{
    int row = blockIdx.x;
    int tid = threadIdx.x;
    const float4* xr = (const float4*)(x + (size_t)row * DD);
    float4 v = xr[tid];
    float s  = v.x + v.y + v.z + v.w;
    float ss = v.x * v.x + v.y * v.y + v.z * v.z + v.w * v.w;
#pragma unroll
    for (int o = 16; o > 0; o >>= 1) {
        s  += __shfl_xor_sync(0xffffffffu, s,  o);
        ss += __shfl_xor_sync(0xffffffffu, ss, o);
    }
    __shared__ float sb[8], sb2[8], stats[2];
    int wid = tid >> 5, lane = tid & 31;
    if (lane == 0) { sb[wid] = s; sb2[wid] = ss; }
    __syncthreads();
    if (tid == 0) {
        float ts = 0.f, tss = 0.f;
#pragma unroll
        for (int i = 0; i < 8; i++) { ts += sb[i]; tss += sb2[i]; }
        float mu  = ts  * (1.0f / DD);
        float var = tss * (1.0f / DD) - mu * mu;
        stats[0] = mu;
        stats[1] = rsqrtf(var + 1e-5f);
    }
    __syncthreads();
    float mu = stats[0], rs = stats[1];
    int c = tid * 4;
    float4 gg = *(const float4*)(gam + c);
    float4 bb = *(const float4*)(bet + c);
    float vals[4];
    vals[0] = to_tf32((v.x - mu) * rs * gg.x + bb.x);
    vals[1] = to_tf32((v.y - mu) * rs * gg.y + bb.y);
    vals[2] = to_tf32((v.z - mu) * rs * gg.z + bb.z);
    vals[3] = to_tf32((v.w - mu) * rs * gg.w + bb.w);
    int base = c & ~7, o8 = c & 7;    // o8 = 0 or 4
    float* op = out + (size_t)row * DD + base;
#pragma unroll
    for (int i = 0; i < 4; i++)
        op[pperm(o8 + i)] = vals[i];
}

// =================== bf16 3-pass GEMM (qkv only; 3-stage pipeline) =========
#define OFF_AH 0
#define OFF_AL 8192
#define OFF_BH 16384
#define OFF_BL 24576
#define STAGE  32768
#define NSTAGE 3
#define TCG_SMEM (NSTAGE * STAGE)

__device__ __forceinline__ uint32_t swz32(int row, int chunk) {
    return (uint32_t)(row * 64 + (((chunk ^ (row >> 1)) & 3) << 4));
}

__device__ __forceinline__ void cp_stage(uint32_t sbase,
                                         const __nv_bfloat16* __restrict__ Ahi,
                                         const __nv_bfloat16* __restrict__ Alo,
                                         const __nv_bfloat16* __restrict__ Bhi,
                                         const __nv_bfloat16* __restrict__ Blo,
                                         int am0, int bn0, int k0, int ldk, int tid)
{
#pragma unroll
    for (int j = 0; j < 2; j++) {
        int v = tid + (j << 8);
        int r = v >> 2, c = v & 3;
        uint32_t so = swz32(r, c);
        size_t goA = (size_t)(am0 + r) * ldk + k0 + c * 8;
        size_t goB = (size_t)(bn0 + r) * ldk + k0 + c * 8;
        cp_async16(sbase + OFF_AH + so, Ahi + goA);
        cp_async16(sbase + OFF_AL + so, Alo + goA);
        cp_async16(sbase + OFF_BH + so, Bhi + goB);
        cp_async16(sbase + OFF_BL + so, Blo + goB);
    }
}

__global__ __launch_bounds__(256, 2)
void tc_gemm_bf(const __nv_bfloat16* __restrict__ Ahi, const __nv_bfloat16* __restrict__ Alo,
                const __nv_bfloat16* __restrict__ Bhi, const __nv_bfloat16* __restrict__ Blo,
                const float* __restrict__ bias,
                __nv_bfloat16* __restrict__ Chi, __nv_bfloat16* __restrict__ Clo,
                int M, int N, int K)
{
    extern __shared__ __align__(128) char smc[];
    uint32_t sb = smem_u32(smc);
    int tid = threadIdx.x, wid = tid >> 5, lane = tid & 31;
    int warp_m = wid >> 1, warp_n = wid & 1;
    int bn = blockIdx.x, bm = blockIdx.y;
    int am0 = bm * 128, bn0 = bn * 128;

    float acc[2][8][4];
#pragma unroll
    for (int mi = 0; mi < 2; mi++)
#pragma unroll
        for (int ni = 0; ni < 8; ni++)
#pragma unroll
            for (int q = 0; q < 4; q++) acc[mi][ni][q] = 0.f;

    int lrA = (lane & 7) + ((lane >> 3) & 1) * 8;
    uint32_t cAoff = (uint32_t)((lane >> 4) << 4);
    uint32_t aB[2], aX[2];
#pragma unroll
    for (int mi = 0; mi < 2; mi++) {
        int row = warp_m * 32 + mi * 16 + lrA;
        aB[mi] = (uint32_t)(row * 64);
        aX[mi] = cAoff ^ (uint32_t)((((row >> 1) & 3)) << 4);
    }
    int lrB = (lane & 7) + ((lane >> 4) & 1) * 8;
    uint32_t cBoff = (uint32_t)(((lane >> 3) & 1) << 4);
    uint32_t bB[4], bX[4];
#pragma unroll
    for (int p = 0; p < 4; p++) {
        int row = warp_n * 64 + p * 16 + lrB;
        bB[p] = (uint32_t)(row * 64);
        bX[p] = cBoff ^ (uint32_t)((((row >> 1) & 3)) << 4);
    }

    int nchunk = K >> 5;
    cp_stage(sb + 0 * STAGE, Ahi, Alo, Bhi, Blo, am0, bn0, 0, K, tid);
    cp_commit();
    cp_stage(sb + 1 * STAGE, Ahi, Alo, Bhi, Blo, am0, bn0, 32, K, tid);
    cp_commit();

    int slot = 0;
    for (int ch = 0; ch < nchunk; ch++) {
        uint32_t st = sb + (uint32_t)slot * STAGE;
        cp_wait<1>();
        __syncthreads();
        int nslot = slot + 2; if (nslot >= NSTAGE) nslot -= NSTAGE;
        if (ch + 2 < nchunk)
            cp_stage(sb + (uint32_t)nslot * STAGE, Ahi, Alo, Bhi, Blo,
                     am0, bn0, (ch + 2) << 5, K, tid);
        cp_commit();

#pragma unroll
        for (int ks = 0; ks < 2; ks++) {
            uint32_t kx = (uint32_t)(ks << 5);
            uint32_t ah[2][4], bh[8][2];
#pragma unroll
            for (int mi = 0; mi < 2; mi++)
                ldsm_x4(ah[mi], st + OFF_AH + aB[mi] + (kx ^ aX[mi]));
#pragma unroll
            for (int p = 0; p < 4; p++) {
                uint32_t r4[4];
                ldsm_x4(r4, st + OFF_BH + bB[p] + (kx ^ bX[p]));
                bh[2 * p][0] = r4[0]; bh[2 * p][1] = r4[1];
                bh[2 * p + 1][0] = r4[2]; bh[2 * p + 1][1] = r4[3];
            }
#pragma unroll
            for (int mi = 0; mi < 2; mi++)
#pragma unroll
                for (int ni = 0; ni < 8; ni++)
                    mma16816(acc[mi][ni], ah[mi], bh[ni]);
            {
                uint32_t al[2][4];
#pragma unroll
                for (int mi = 0; mi < 2; mi++)
                    ldsm_x4(al[mi], st + OFF_AL + aB[mi] + (kx ^ aX[mi]));
#pragma unroll
                for (int mi = 0; mi < 2; mi++)
#pragma unroll
                    for (int ni = 0; ni < 8; ni++)
                        mma16816(acc[mi][ni], al[mi], bh[ni]);
            }
            {
                uint32_t bl[8][2];
#pragma unroll
                for (int p = 0; p < 4; p++) {
                    uint32_t r4[4];
                    ldsm_x4(r4, st + OFF_BL + bB[p] + (kx ^ bX[p]));
                    bl[2 * p][0] = r4[0]; bl[2 * p][1] = r4[1];
                    bl[2 * p + 1][0] = r4[2]; bl[2 * p + 1][1] = r4[3];
                }
#pragma unroll
                for (int mi = 0; mi < 2; mi++)
#pragma unroll
                    for (int ni = 0; ni < 8; ni++)
                        mma16816(acc[mi][ni], ah[mi], bl[ni]);
            }
        }
        slot++; if (slot >= NSTAGE) slot = 0;
    }

    int g = lane >> 2, tig = lane & 3;
#pragma unroll
    for (int mi = 0; mi < 2; mi++) {
#pragma unroll
        for (int half = 0; half < 2; half++) {
            int r = bm * 128 + warp_m * 32 + mi * 16 + g + half * 8;
#pragma unroll
            for (int ni = 0; ni < 8; ni++) {
                int c = bn * 128 + warp_n * 64 + ni * 8 + tig * 2;
                float v0 = acc[mi][ni][half * 2 + 0];
                float v1 = acc[mi][ni][half * 2 + 1];
                float2 bv = *(const float2*)(bias + c);
                v0 += bv.x; v1 += bv.y;
                store_hilo2(Chi, Clo, (size_t)r * N + c, v0, v1);
            }
        }
    }
}

// ===== tf32 1-pass GEMM (k-permuted, XOR-swizzled rows, LDS.64 frags) ======
// Tiles: 128 rows x 16 floats (64B rows), chunk c of row r at (c ^ (r&3)).
// 128x128 CTA, 256 thr (8 warps 2m x 4n, 64x32 warp tile), K-chunks of 16.
// EPI: 1 = gelu(+bias) -> tf32 fp32 k-permuted ; 2 = +bias+res -> fp32
#define TTILEB 8192                 // bytes per 128x16 float tile
#define TSTB   (2 * TTILEB)         // bytes per stage (A + B)
#define TSTF   (TSTB / 4)           // floats per stage
#define TF_SMEM (3 * TSTB)          // 49152 bytes

__device__ __forceinline__ void cp_stage_tf(uint32_t sbase,
                                            const float* __restrict__ A,
                                            const float* __restrict__ Bt,
                                            int am0, int bn0, int k0, int ldk, int tid)
{
#pragma unroll
    for (int j = 0; j < 4; j++) {
        int idx = tid + (j << 8);        // 0..1023
        int tile = idx >> 9;
        int w = idx & 511;
        int r = w >> 2, c = w & 3;       // row, 16B chunk
        uint32_t dst = sbase + (uint32_t)tile * TTILEB
                     + (uint32_t)(r * 64) + (uint32_t)(((c ^ (r & 3)) << 4));
        const float* src = (tile ? Bt + (size_t)(bn0 + r) * ldk : A + (size_t)(am0 + r) * ldk)
                           + k0 + c * 4;
        cp_async16(dst, src);
    }
}

template <int EPI>
__global__ __launch_bounds__(256, 2)
void tf_gemm(const float* __restrict__ A, const float* __restrict__ Bt,
             const float* __restrict__ bias, const float* __restrict__ res,
             float* __restrict__ Cf, int M, int N, int K)
{
    extern __shared__ __align__(128) float smf[];
    int tid = threadIdx.x, wid = tid >> 5, lane = tid & 31;
    int warp_m = wid >> 2, warp_n = wid & 3;     // 2m x 4n
    int g = lane >> 2, tig = lane & 3;
    int bn = blockIdx.x, bm = blockIdx.y;
    int am0 = bm * 128, bn0 = bn * 128;

    float acc[4][4][4];
#pragma unroll
    for (int mi = 0; mi < 4; mi++)
#pragma unroll
        for (int ni = 0; ni < 4; ni++)
#pragma unroll
            for (int q = 0; q < 4; q++) acc[mi][ni][q] = 0.f;

    int nchunk = K >> 4;
    uint32_t sb = smem_u32(smf);
    cp_stage_tf(sb + 0 * TSTB, A, Bt, am0, bn0, 0, K, tid);
    cp_commit();
    cp_stage_tf(sb + 1 * TSTB, A, Bt, am0, bn0, 16, K, tid);
    cp_commit();

    int subo = (tig & 1) * 2;
    int cjt  = tig >> 1;

    int slot = 0;
    for (int ch = 0; ch < nchunk; ch++) {
        cp_wait<1>();
        __syncthreads();
        int nslot = slot + 2; if (nslot >= 3) nslot -= 3;
        if (ch + 2 < nchunk)
            cp_stage_tf(sb + (uint32_t)nslot * TSTB, A, Bt, am0, bn0,
                        (ch + 2) << 4, K, tid);
        cp_commit();

        const float* As = smf + slot * TSTF;
        const float* Bs = As + (TTILEB / 4);

#pragma unroll
        for (int ks = 0; ks < 2; ks++) {
            int cj = ks * 2 + cjt;
            uint32_t a[4][4];
#pragma unroll
            for (int mi = 0; mi < 4; mi++) {
                int r0 = warp_m * 64 + mi * 16 + g;
                int r1 = r0 + 8;
                float2 f0 = *(const float2*)&As[r0 * 16 + ((cj ^ (r0 & 3)) << 2) + subo];
                float2 f1 = *(const float2*)&As[r1 * 16 + ((cj ^ (r1 & 3)) << 2) + subo];
                a[mi][0] = __float_as_uint(f0.x);
                a[mi][1] = __float_as_uint(f1.x);
                a[mi][2] = __float_as_uint(f0.y);
                a[mi][3] = __float_as_uint(f1.y);
            }
            uint32_t b[4][2];
#pragma unroll
            for (int ni = 0; ni < 4; ni++) {
                int rn = warp_n * 32 + ni * 8 + g;
                float2 f = *(const float2*)&Bs[rn * 16 + ((cj ^ (rn & 3)) << 2) + subo];
                b[ni][0] = __float_as_uint(f.x);
                b[ni][1] = __float_as_uint(f.y);
            }
#pragma unroll
            for (int mi = 0; mi < 4; mi++)
#pragma unroll
                for (int ni = 0; ni < 4; ni++)
                    mma_tf32(acc[mi][ni], a[mi], b[ni]);
        }
        slot++; if (slot >= 3) slot = 0;
    }

#pragma unroll
    for (int mi = 0; mi < 4; mi++) {
#pragma unroll
        for (int half = 0; half < 2; half++) {
            int r = bm * 128 + warp_m * 64 + mi * 16 + g + half * 8;
#pragma unroll
            for (int ni = 0; ni < 4; ni++) {
                int c = bn * 128 + warp_n * 32 + ni * 8 + tig * 2;
                float v0 = acc[mi][ni][half * 2 + 0];
                float v1 = acc[mi][ni][half * 2 + 1];
                float2 bv = *(const float2*)(bias + c);
                v0 += bv.x; v1 += bv.y;
                size_t rowb = (size_t)r * N;
                if (EPI == 1) {
                    int cb = c & ~7, j = c & 7;
                    Cf[rowb + cb + pperm(j)]     = to_tf32(gelu_fast(v0));
                    Cf[rowb + cb + pperm(j + 1)] = to_tf32(gelu_fast(v1));
                } else {
                    float2 rv = *(const float2*)(res + rowb + c);
                    v0 += rv.x; v1 += rv.y;
                    *(float2*)(Cf + rowb + c) = make_float2(v0, v1);
                }
            }
        }
    }
}

// ============ Tensor-core causal flash attention (cp.async pipelined) ======
#define AQH 0
#define AQL 8192
#define ASTG 16384
#define SKH 0
#define SKL 8192
#define SVH 16384
#define SVL 24576
#define SSTG 32768
#define ATT_SMEM (ASTG + 3 * SSTG)   // 112 KB

__device__ __forceinline__ void attn_cp_kv(uint32_t stg,
                                           const __nv_bfloat16* __restrict__ qh,
                                           const __nv_bfloat16* __restrict__ ql,
                                           size_t rowbase, int hoff, int tid)
{
#pragma unroll
    for (int j = 0; j < 4; j++) {
        int idx = tid + (j << 7);
        int r = idx >> 3, c = idx & 7;
        uint32_t ad = (uint32_t)(r * 128) + (uint32_t)(((c ^ r) & 7) << 4);
        size_t gK = rowbase + (size_t)r * (3 * DD) + DD + hoff + c * 8;
        size_t gV = rowbase + (size_t)r * (3 * DD) + 2 * DD + hoff + c * 8;
        cp_async16(stg + SKH + ad, qh + gK);
        cp_async16(stg + SKL + ad, ql + gK);
        cp_async16(stg + SVH + ad, qh + gV);
        cp_async16(stg + SVL + ad, ql + gV);
    }
}

__global__ __launch_bounds__(128)
void attn_kernel(const __nv_bfloat16* __restrict__ qkvh,
                 const __nv_bfloat16* __restrict__ qkvl,
                 float* __restrict__ oat)
{
    extern __shared__ __align__(128) char sma[];
    uint32_t sb = smem_u32(sma);
    int qt = (int)gridDim.x - 1 - (int)blockIdx.x;
    int h = blockIdx.y, b = blockIdx.z;
    int tid = threadIdx.x, warp = tid >> 5, lane = tid & 31;
    int q0 = qt * 64;
    int g = lane >> 2, tig = lane & 3;
    int hoff = h * HDIM;

    {
        size_t rowQ = (size_t)(b * SS + q0) * (3 * DD);
#pragma unroll
        for (int j = 0; j < 4; j++) {
            int idx = tid + (j << 7);
            int r = idx >> 3, c = idx & 7;
            uint32_t ad = (uint32_t)(r * 128) + (uint32_t)(((c ^ r) & 7) << 4);
            size_t gQ = rowQ + (size_t)r * (3 * DD) + hoff + c * 8;
            cp_async16(sb + AQH + ad, qkvh + gQ);
            cp_async16(sb + AQL + ad, qkvl + gQ);
        }
        attn_cp_kv(sb + ASTG, qkvh, qkvl, (size_t)(b * SS) * (3 * DD), hoff, tid);
        cp_commit();
        attn_cp_kv(sb + ASTG + SSTG, qkvh, qkvl,
                   (size_t)(b * SS + 64) * (3 * DD), hoff, tid);
        cp_commit();
    }

    int lrA = (lane & 7) + ((lane >> 3) & 1) * 8;
    uint32_t cA = (uint32_t)((lane >> 4) << 4);
    int rowA = warp * 16 + lrA;
    uint32_t aBase = (uint32_t)(rowA * 128);
    uint32_t aMask = (uint32_t)((rowA & 7) << 4);

    int lrB = (lane & 7) + ((lane >> 4) & 1) * 8;
    uint32_t cB = (uint32_t)(((lane >> 3) & 1) << 4);

    int lrV = (lane & 7) + ((lane >> 3) & 1) * 8;
    uint32_t cV = (uint32_t)(((lane >> 4) & 1) << 4);

    float oacc[8][4];
    float mA = -1e30f, mB = -1e30f, lA = 0.f, lB = 0.f;
#pragma unroll
    for (int t = 0; t < 8; t++)
#pragma unroll
        for (int q = 0; q < 4; q++) oacc[t][q] = 0.f;

    int slot = 0;
    for (int kt = 0; kt <= qt; kt++) {
        uint32_t st = sb + ASTG + (uint32_t)slot * SSTG;
        cp_wait<1>();
        __syncthreads();
        int nslot = slot + 2; if (nslot >= 3) nslot -= 3;
        if (kt + 2 <= qt)
            attn_cp_kv(sb + ASTG + (uint32_t)nslot * SSTG, qkvh, qkvl,
                       (size_t)(b * SS + (kt + 2) * 64) * (3 * DD), hoff, tid);
        cp_commit();

        float sacc[8][4];
#pragma unroll
        for (int t = 0; t < 8; t++)
#pragma unroll
            for (int q = 0; q < 4; q++) sacc[t][q] = 0.f;

#pragma unroll
        for (int ks = 0; ks < 4; ks++) {
            uint32_t kx = (uint32_t)(ks * 32);
            uint32_t qh4[4], ql4[4], kh[8][2];
            ldsm_x4(qh4, sb + AQH + aBase + ((kx + cA) ^ aMask));
            ldsm_x4(ql4, sb + AQL + aBase + ((kx + cA) ^ aMask));
#pragma unroll
            for (int p = 0; p < 4; p++) {
                int rowB = p * 16 + lrB;
                uint32_t r4[4];
                ldsm_x4(r4, st + SKH + (uint32_t)(rowB * 128) +
                            ((kx + cB) ^ (uint32_t)((rowB & 7) << 4)));
                kh[2 * p][0] = r4[0]; kh[2 * p][1] = r4[1];
                kh[2 * p + 1][0] = r4[2]; kh[2 * p + 1][1] = r4[3];
            }
#pragma unroll
            for (int t = 0; t < 8; t++) mma16816(sacc[t], qh4, kh[t]);
#pragma unroll
            for (int t = 0; t < 8; t++) mma16816(sacc[t], ql4, kh[t]);
            {
                uint32_t kl[8][2];
#pragma unroll
                for (int p = 0; p < 4; p++) {
                    int rowB = p * 16 + lrB;
                    uint32_t r4[4];
                    ldsm_x4(r4, st + SKL + (uint32_t)(rowB * 128) +
                                ((kx + cB) ^ (uint32_t)((rowB & 7) << 4)));
                    kl[2 * p][0] = r4[0]; kl[2 * p][1] = r4[1];
                    kl[2 * p + 1][0] = r4[2]; kl[2 * p + 1][1] = r4[3];
                }
#pragma unroll
                for (int t = 0; t < 8; t++) mma16816(sacc[t], qh4, kl[t]);
            }
        }

#pragma unroll
        for (int t = 0; t < 8; t++) {
            sacc[t][0] *= 0.125f; sacc[t][1] *= 0.125f;
            sacc[t][2] *= 0.125f; sacc[t][3] *= 0.125f;
        }

        if (kt == qt) {
            int qlocA = warp * 16 + g, qlocB = qlocA + 8;
#pragma unroll
            for (int t = 0; t < 8; t++) {
                int k0c = t * 8 + tig * 2;
                if (k0c > qlocA)     sacc[t][0] = -1e30f;
                if (k0c + 1 > qlocA) sacc[t][1] = -1e30f;
                if (k0c > qlocB)     sacc[t][2] = -1e30f;
                if (k0c + 1 > qlocB) sacc[t][3] = -1e30f;
            }
        }

        float maA = -1e30f, maB = -1e30f;
#pragma unroll
        for (int t = 0; t < 8; t++) {
            maA = fmaxf(maA, fmaxf(sacc[t][0], sacc[t][1]));
            maB = fmaxf(maB, fmaxf(sacc[t][2], sacc[t][3]));
        }
        maA = fmaxf(maA, __shfl_xor_sync(0xffffffffu, maA, 1));
        maA = fmaxf(maA, __shfl_xor_sync(0xffffffffu, maA, 2));
        maB = fmaxf(maB, __shfl_xor_sync(0xffffffffu, maB, 1));
        maB = fmaxf(maB, __shfl_xor_sync(0xffffffffu, maB, 2));
        float nmA = fmaxf(mA, maA), nmB = fmaxf(mB, maB);
        float corrA = fexp(mA - nmA), corrB = fexp(mB - nmB);
        mA = nmA; mB = nmB;
        float sumA = 0.f, sumB = 0.f;
#pragma unroll
        for (int t = 0; t < 8; t++) {
            sacc[t][0] = fexp(sacc[t][0] - nmA);
            sacc[t][1] = fexp(sacc[t][1] - nmA);
            sacc[t][2] = fexp(sacc[t][2] - nmB);
            sacc[t][3] = fexp(sacc[t][3] - nmB);
            sumA += sacc[t][0] + sacc[t][1];
            sumB += sacc[t][2] + sacc[t][3];
        }
        sumA += __shfl_xor_sync(0xffffffffu, sumA, 1);
        sumA += __shfl_xor_sync(0xffffffffu, sumA, 2);
        sumB += __shfl_xor_sync(0xffffffffu, sumB, 1);
        sumB += __shfl_xor_sync(0xffffffffu, sumB, 2);
        lA = lA * corrA + sumA;
        lB = lB * corrB + sumB;
#pragma unroll
        for (int t = 0; t < 8; t++) {
            oacc[t][0] *= corrA; oacc[t][1] *= corrA;
            oacc[t][2] *= corrB; oacc[t][3] *= corrB;
        }

        uint32_t ph[4][4], pl[4][4];
#pragma unroll
        for (int p = 0; p < 4; p++) {
#pragma unroll
            for (int q = 0; q < 4; q++) {
                int t = 2 * p + (q >> 1);
                float a = sacc[t][(q & 1) * 2 + 0];
                float bv = sacc[t][(q & 1) * 2 + 1];
                __nv_bfloat16 ah2 = __float2bfloat16(a), bh2 = __float2bfloat16(bv);
                __nv_bfloat162 th = __halves2bfloat162(ah2, bh2);
                ph[p][q] = *(uint32_t*)&th;
                __nv_bfloat162 tl = __halves2bfloat162(
                    __float2bfloat16(a - __bfloat162float(ah2)),
                    __float2bfloat16(bv - __bfloat162float(bh2)));
                pl[p][q] = *(uint32_t*)&tl;
            }
        }

#pragma unroll
        for (int ks = 0; ks < 4; ks++) {
            int rowV = ks * 16 + lrV;
            uint32_t vMask = (uint32_t)((rowV & 7) << 4);
            uint32_t vbh[8][2], vbl[8][2];
#pragma unroll
            for (int j = 0; j < 4; j++) {
                uint32_t cb = (uint32_t)(j * 32) + cV;
                uint32_t r4[4];
                ldsm_x4_t(r4, st + SVH + (uint32_t)(rowV * 128) + (cb ^ vMask));
                vbh[2 * j][0] = r4[0]; vbh[2 * j][1] = r4[1];
                vbh[2 * j + 1][0] = r4[2]; vbh[2 * j + 1][1] = r4[3];
            }
#pragma unroll
            for (int j = 0; j < 4; j++) {
                uint32_t cb = (uint32_t)(j * 32) + cV;
                uint32_t r4[4];
                ldsm_x4_t(r4, st + SVL + (uint32_t)(rowV * 128) + (cb ^ vMask));
                vbl[2 * j][0] = r4[0]; vbl[2 * j][1] = r4[1];
                vbl[2 * j + 1][0] = r4[2]; vbl[2 * j + 1][1] = r4[3];
            }
#pragma unroll
            for (int t = 0; t < 8; t++) mma16816(oacc[t], ph[ks], vbh[t]);
#pragma unroll
            for (int t = 0; t < 8; t++) mma16816(oacc[t], pl[ks], vbh[t]);
#pragma unroll
            for (int t = 0; t < 8; t++) mma16816(oacc[t], ph[ks], vbl[t]);
        }
        slot++; if (slot >= 3) slot = 0;
    }

    // ---- normalize + k-permuted write (feeds o-proj tf32 GEMM) ----
    float invA = 1.0f / lA, invB = 1.0f / lB;
    int rowAg = b * SS + q0 + warp * 16 + g;
    int rowBg = rowAg + 8;
#pragma unroll
    for (int t = 0; t < 8; t++) {
        int gbase = h * HDIM + t * 8;
        int j0 = tig * 2;
        float* pA = oat + (size_t)rowAg * DD + gbase;
        float* pB = oat + (size_t)rowBg * DD + gbase;
        pA[pperm(j0)]     = to_tf32(oacc[t][0] * invA);
        pA[pperm(j0 + 1)] = to_tf32(oacc[t][1] * invA);
        pB[pperm(j0)]     = to_tf32(oacc[t][2] * invB);
        pB[pperm(j0 + 1)] = to_tf32(oacc[t][3] * invB);
    }
}

// ---------------- launch ---------------------------------------------------
extern "C" void kernel_launch(void* const* d_in, const int* in_sizes, int n_in,
                              void* d_out, int out_size)
{
    const float* x    = (const float*)d_in[0];
    const float* pos  = (const float*)d_in[1];
    const float* ln1g = (const float*)d_in[2];
    const float* ln1b = (const float*)d_in[3];
    const float* wqkv = (const float*)d_in[4];
    const float* bqkv = (const float*)d_in[5];
    const float* wo   = (const float*)d_in[6];
    const float* bo   = (const float*)d_in[7];
    const float* ln2g = (const float*)d_in[8];
    const float* ln2b = (const float*)d_in[9];
    const float* wfc  = (const float*)d_in[10];
    const float* bfc  = (const float*)d_in[11];
    const float* wpr  = (const float*)d_in[12];
    const float* bpr  = (const float*)d_in[13];
    float* out = (float*)d_out;

    __nv_bfloat16 *p_h_hi, *p_h_lo, *p_qkvh, *p_qkvl, *p_wqkv_hi, *p_wqkv_lo;
    float *p_at, *p_x2, *p_m, *p_ff, *p_woT, *p_wfcT, *p_wprT;
    cudaGetSymbolAddress((void**)&p_h_hi, g_h_hi);   cudaGetSymbolAddress((void**)&p_h_lo, g_h_lo);
    cudaGetSymbolAddress((void**)&p_qkvh, g_qkvh);   cudaGetSymbolAddress((void**)&p_qkvl, g_qkvl);
    cudaGetSymbolAddress((void**)&p_at, g_at);
    cudaGetSymbolAddress((void**)&p_x2, g_x2);
    cudaGetSymbolAddress((void**)&p_m, g_m);
    cudaGetSymbolAddress((void**)&p_ff, g_ff);
    cudaGetSymbolAddress((void**)&p_wqkv_hi, g_wqkv_hi); cudaGetSymbolAddress((void**)&p_wqkv_lo, g_wqkv_lo);
    cudaGetSymbolAddress((void**)&p_woT, g_woT);
    cudaGetSymbolAddress((void**)&p_wfcT, g_wfcT);
    cudaGetSymbolAddress((void**)&p_wprT, g_wprT);

    cudaFuncSetAttribute(tc_gemm_bf, cudaFuncAttributeMaxDynamicSharedMemorySize, TCG_SMEM);
    cudaFuncSetAttribute(tf_gemm<1>, cudaFuncAttributeMaxDynamicSharedMemorySize, TF_SMEM);
    cudaFuncSetAttribute(tf_gemm<2>, cudaFuncAttributeMaxDynamicSharedMemorySize, TF_SMEM);
    cudaFuncSetAttribute(attn_kernel, cudaFuncAttributeMaxDynamicSharedMemorySize, ATT_SMEM);

    dim3 tb(32, 8);
    wsplit_t<<<dim3(3 * DD / 32, DD / 32), tb>>>(wqkv, p_wqkv_hi, p_wqkv_lo, DD, 3 * DD);
    wtrans<<<dim3(DD / 32, DD / 32), tb>>>(wo, p_woT, DD, DD);
    wtrans<<<dim3(DFFN / 32, DD / 32), tb>>>(wfc, p_wfcT, DD, DFFN);
    wtrans<<<dim3(DD / 32, DFFN / 32), tb>>>(wpr, p_wprT, DFFN, DD);

    // 1) h = LN1(x) + pos -> bf16 hi/lo
    ln_bf<<<ROWS, 256>>>(x, ln1g, ln1b, pos, p_h_hi, p_h_lo);

    // 2) qkv = h @ w_qkv + b_qkv -> bf16 hi/lo (3-pass, accuracy-critical)
    tc_gemm_bf<<<dim3(3 * DD / 128, ROWS / 128), 256, TCG_SMEM>>>(
        p_h_hi, p_h_lo, p_wqkv_hi, p_wqkv_lo, bqkv,
        p_qkvh, p_qkvl, ROWS, 3 * DD, DD);

    // 3) causal attention -> tf32 fp32, k-permuted
    attn_kernel<<<dim3(SS / 64, HH, BB), 128, ATT_SMEM>>>(p_qkvh, p_qkvl, p_at);

    // 4) x2 = x + attn @ w_o + b_o (tf32)
    tf_gemm<2><<<dim3(DD / 128, ROWS / 128), 256, TF_SMEM>>>(
        p_at, p_woT, bo, x, p_x2, ROWS, DD, DD);

    // 5) m = LN2(x2) -> tf32 fp32, k-permuted
    ln_tf<<<ROWS, 256>>>(p_x2, ln2g, ln2b, p_m);

    // 6) ff = gelu(m @ w_fc + b_fc) (tf32) -> tf32 fp32, k-permuted
    tf_gemm<1><<<dim3(DFFN / 128, ROWS / 128), 256, TF_SMEM>>>(
        p_m, p_wfcT, bfc, nullptr, p_ff, ROWS, DFFN, DD);

    // 7) out = x2 + ff @ w_proj + b_proj (tf32)
    tf_gemm<2><<<dim3(DD / 128, ROWS / 128), 256, TF_SMEM>>>(
        p_ff, p_wprT, bpr, p_x2, out, ROWS, DD, DFFN);
}

// round 15
// speedup vs baseline: 1.0359x; 1.0102x over previous
#include <cuda_runtime.h>
#include <cuda_bf16.h>
#include <math.h>
#include <stdint.h>

// Problem constants
#define BB   2
#define SS   2048
#define DD   1024
#define HH   16
#define HDIM 64
#define DFFN 4096
#define ROWS (BB * SS)   // 4096

// -------- scratch (static device globals; no allocation) --------
__device__ __align__(16) __nv_bfloat16 g_h_hi[ROWS * DD], g_h_lo[ROWS * DD];
__device__ __align__(16) __nv_bfloat16 g_qkvh[ROWS * 3 * DD], g_qkvl[ROWS * 3 * DD];
__device__ __align__(16) float         g_at[ROWS * DD];          // tf32, k-permuted
__device__ __align__(16) float         g_x2[ROWS * DD];
__device__ __align__(16) float         g_m[ROWS * DD];           // tf32, k-permuted
__device__ __align__(16) float         g_ff[ROWS * DFFN];        // tf32, k-permuted
__device__ __align__(16) __nv_bfloat16 g_wqkv_hi[3 * DD * DD], g_wqkv_lo[3 * DD * DD];
__device__ __align__(16) float         g_woT[DD * DD];           // k-permuted
__device__ __align__(16) float         g_wfcT[DFFN * DD];        // k-permuted
__device__ __align__(16) float         g_wprT[DD * DFFN];        // k-permuted

// -------- side streams/events for graph fork-join (host objects only) ------
static cudaStream_t g_s1 = nullptr, g_s2 = nullptr;
static cudaEvent_t  g_ev0 = nullptr, g_ev1 = nullptr, g_ev2 = nullptr;
struct _StreamInit {
    _StreamInit() {
        cudaStreamCreateWithFlags(&g_s1, cudaStreamNonBlocking);
        cudaStreamCreateWithFlags(&g_s2, cudaStreamNonBlocking);
        cudaEventCreateWithFlags(&g_ev0, cudaEventDisableTiming);
        cudaEventCreateWithFlags(&g_ev1, cudaEventDisableTiming);
        cudaEventCreateWithFlags(&g_ev2, cudaEventDisableTiming);
    }
};
static _StreamInit _stream_init_once;

// ======================= portable PTX helpers ==============================
__device__ __forceinline__ uint32_t smem_u32(const void* p) {
    uint32_t a;
    asm("{ .reg .u64 t; cvta.to.shared.u64 t, %1; cvt.u32.u64 %0, t; }" : "=r"(a) : "l"(p));
    return a;
}

__device__ __forceinline__ void cp_async16(uint32_t saddr, const void* gaddr) {
    asm volatile("cp.async.cg.shared.global [%0], [%1], 16;" :: "r"(saddr), "l"(gaddr));
}
__device__ __forceinline__ void cp_commit() {
    asm volatile("cp.async.commit_group;" ::: "memory");
}
template <int N>
__device__ __forceinline__ void cp_wait() {
    asm volatile("cp.async.wait_group %0;" :: "n"(N) : "memory");
}

__device__ __forceinline__ void ldsm_x4(uint32_t* r, uint32_t addr) {
    asm volatile("ldmatrix.sync.aligned.m8n8.x4.shared.b16 {%0,%1,%2,%3}, [%4];"
        : "=r"(r[0]), "=r"(r[1]), "=r"(r[2]), "=r"(r[3]) : "r"(addr));
}
__device__ __forceinline__ void ldsm_x4_t(uint32_t* r, uint32_t addr) {
    asm volatile("ldmatrix.sync.aligned.m8n8.x4.trans.shared.b16 {%0,%1,%2,%3}, [%4];"
        : "=r"(r[0]), "=r"(r[1]), "=r"(r[2]), "=r"(r[3]) : "r"(addr));
}

__device__ __forceinline__ void mma16816(float* c, const uint32_t* a, const uint32_t* b) {
    asm volatile(
        "mma.sync.aligned.m16n8k16.row.col.f32.bf16.bf16.f32 "
        "{%0,%1,%2,%3}, {%4,%5,%6,%7}, {%8,%9}, {%0,%1,%2,%3};"
        : "+f"(c[0]), "+f"(c[1]), "+f"(c[2]), "+f"(c[3])
        : "r"(a[0]), "r"(a[1]), "r"(a[2]), "r"(a[3]), "r"(b[0]), "r"(b[1]));
}

__device__ __forceinline__ void mma_tf32(float* c, const uint32_t* a, const uint32_t* b) {
    asm volatile(
        "mma.sync.aligned.m16n8k8.row.col.f32.tf32.tf32.f32 "
        "{%0,%1,%2,%3}, {%4,%5,%6,%7}, {%8,%9}, {%0,%1,%2,%3};"
        : "+f"(c[0]), "+f"(c[1]), "+f"(c[2]), "+f"(c[3])
        : "r"(a[0]), "r"(a[1]), "r"(a[2]), "r"(a[3]), "r"(b[0]), "r"(b[1]));
}

__device__ __forceinline__ float to_tf32(float x) {
    uint32_t o;
    asm("cvt.rna.tf32.f32 %0, %1;" : "=r"(o) : "f"(x));
    return __uint_as_float(o);
}

// k-permutation within 8-groups: position 2t holds k=t, position 2t+1 holds k=t+4
__device__ __forceinline__ int pperm(int j) { return ((j & 3) << 1) | (j >> 2); }

// ======================= small math helpers ================================
// fast exp on the FMA pipe (no MUFU), clamped both ends
__device__ __forceinline__ float fexp(float x) {
    float y = fminf(fmaxf(x * 1.4426950408889634f, -126.0f), 126.0f);
    float z = y + 12582912.0f;
    int   n = __float_as_int(z) - 0x4B400000;
    float f = y - (z - 12582912.0f);
    float p = 0.0013333558146f;
    p = fmaf(p, f, 0.0096181291076f);
    p = fmaf(p, f, 0.0555041086648f);
    p = fmaf(p, f, 0.2402265069591f);
    p = fmaf(p, f, 0.6931471805599f);
    p = fmaf(p, f, 1.0f);
    return p * __int_as_float((n + 127) << 23);
}

// gelu (tanh approx) via exact identity: 0.5x(1+tanh z) = x / (1 + e^{-2z})
__device__ __forceinline__ float gelu_fast(float x) {
    float x2 = x * x;
    float z2 = 1.5957691216057308f * fmaf(0.044715f * x2, x, x);  // 2z
    float e = fexp(-z2);
    return __fdividef(x, 1.0f + e);
}

__device__ __forceinline__ void store_hilo4(__nv_bfloat16* oh, __nv_bfloat16* ol,
                                            size_t idx, float4 v)
{
    __nv_bfloat16 h0 = __float2bfloat16(v.x), h1 = __float2bfloat16(v.y);
    __nv_bfloat16 h2 = __float2bfloat16(v.z), h3 = __float2bfloat16(v.w);
    float l0 = v.x - __bfloat162float(h0), l1 = v.y - __bfloat162float(h1);
    float l2 = v.z - __bfloat162float(h2), l3 = v.w - __bfloat162float(h3);
    *(__nv_bfloat162*)(oh + idx)     = __halves2bfloat162(h0, h1);
    *(__nv_bfloat162*)(oh + idx + 2) = __halves2bfloat162(h2, h3);
    *(__nv_bfloat162*)(ol + idx)     = __halves2bfloat162(__float2bfloat16(l0), __float2bfloat16(l1));
    *(__nv_bfloat162*)(ol + idx + 2) = __halves2bfloat162(__float2bfloat16(l2), __float2bfloat16(l3));
}

__device__ __forceinline__ void store_hilo2(__nv_bfloat16* oh, __nv_bfloat16* ol,
                                            size_t idx, float a, float b)
{
    __nv_bfloat16 h0 = __float2bfloat16(a), h1 = __float2bfloat16(b);
    float l0 = a - __bfloat162float(h0), l1 = b - __bfloat162float(h1);
    *(__nv_bfloat162*)(oh + idx) = __halves2bfloat162(h0, h1);
    *(__nv_bfloat162*)(ol + idx) = __halves2bfloat162(__float2bfloat16(l0), __float2bfloat16(l1));
}

// ============ weight transpose + bf16 split (qkv only) =====================
__global__ void wsplit_t(const float* __restrict__ W, __nv_bfloat16* __restrict__ Th,
                         __nv_bfloat16* __restrict__ Tl, int K, int N)
{
    __shared__ float t[32][33];
    int bx = blockIdx.x, by = blockIdx.y;
    int x = threadIdx.x, y = threadIdx.y;
#pragma unroll
    for (int i = 0; i < 32; i += 8)
        t[y + i][x] = W[(size_t)(by * 32 + y + i) * N + bx * 32 + x];
    __syncthreads();
#pragma unroll
    for (int i = 0; i < 32; i += 8) {
        float v = t[x][y + i];
        __nv_bfloat16 h = __float2bfloat16(v);
        float lo = v - __bfloat162float(h);
        size_t o = (size_t)(bx * 32 + y + i) * K + by * 32 + x;
        Th[o] = h;
        Tl[o] = __float2bfloat16(lo);
    }
}

// ============ weight transpose + tf32 round, k-permuted (others) ===========
__global__ void wtrans(const float* __restrict__ W, float* __restrict__ T, int K, int N)
{
    __shared__ float t[32][33];
    int bx = blockIdx.x, by = blockIdx.y;
    int x = threadIdx.x, y = threadIdx.y;
#pragma unroll
    for (int i = 0; i < 32; i += 8)
        t[y + i][x] = W[(size_t)(by * 32 + y + i) * N + bx * 32 + x];
    __syncthreads();
    int kp = by * 32 + (x & ~7) + pperm(x & 7);   // permuted k index
#pragma unroll
    for (int i = 0; i < 32; i += 8)
        T[(size_t)(bx * 32 + y + i) * K + kp] = to_tf32(t[x][y + i]);
}

// ---------------- LayerNorm -> bf16 hi/lo (feeds bf16 GEMM) ----------------
__global__ void ln_bf(const float* __restrict__ x,
                      const float* __restrict__ gam,
                      const float* __restrict__ bet,
                      const float* __restrict__ pos,
                      __nv_bfloat16* __restrict__ oh,
                      __nv_bfloat16* __restrict__ ol)
{
    int row = blockIdx.x;
    int tid = threadIdx.x;
    const float4* xr = (const float4*)(x + (size_t)row * DD);
    float4 v = xr[tid];
    float s  = v.x + v.y + v.z + v.w;
    float ss = v.x * v.x + v.y * v.y + v.z * v.z + v.w * v.w;
#pragma unroll
    for (int o = 16; o > 0; o >>= 1) {
        s  += __shfl_xor_sync(0xffffffffu, s,  o);
        ss += __shfl_xor_sync(0xffffffffu, ss, o);
    }
    __shared__ float sb[8], sb2[8], stats[2];
    int wid = tid >> 5, lane = tid & 31;
    if (lane == 0) { sb[wid] = s; sb2[wid] = ss; }
    __syncthreads();
    if (tid == 0) {
        float ts = 0.f, tss = 0.f;
#pragma unroll
        for (int i = 0; i < 8; i++) { ts += sb[i]; tss += sb2[i]; }
        float mu  = ts  * (1.0f / DD);
        float var = tss * (1.0f / DD) - mu * mu;
        stats[0] = mu;
        stats[1] = rsqrtf(var + 1e-5f);
    }
    __syncthreads();
    float mu = stats[0], rs = stats[1];
    int c = tid * 4;
    float4 gg = *(const float4*)(gam + c);
    float4 bb = *(const float4*)(bet + c);
    float4 o4;
    o4.x = (v.x - mu) * rs * gg.x + bb.x;
    o4.y = (v.y - mu) * rs * gg.y + bb.y;
    o4.z = (v.z - mu) * rs * gg.z + bb.z;
    o4.w = (v.w - mu) * rs * gg.w + bb.w;
    if (pos) {
        int srow = row % SS;
        float4 p = *(const float4*)(pos + (size_t)srow * DD + c);
        o4.x += p.x; o4.y += p.y; o4.z += p.z; o4.w += p.w;
    }
    store_hilo4(oh, ol, (size_t)row * DD + c, o4);
}

// ---------------- LayerNorm -> tf32-rounded fp32, k-permuted ---------------
__global__ void ln_tf(const float* __restrict__ x,
                      const float* __restrict__ gam,
                      const float* __restrict__ bet,
                      float* __restrict__ out)
{
    int row = blockIdx.x;
    int tid = threadIdx.x;
    const float4* xr = (const float4*)(x + (size_t)row * DD);
    float4 v = xr[tid];
    float s  = v.x + v.y + v.z + v.w;
    float ss = v.x * v.x + v.y * v.y + v.z * v.z + v.w * v.w;
#pragma unroll
    for (int o = 16; o > 0; o >>= 1) {
        s  += __shfl_xor_sync(0xffffffffu, s,  o);
        ss += __shfl_xor_sync(0xffffffffu, ss, o);
    }
    __shared__ float sb[8], sb2[8], stats[2];
    int wid = tid >> 5, lane = tid & 31;
    if (lane == 0) { sb[wid] = s; sb2[wid] = ss; }
    __syncthreads();
    if (tid == 0) {
        float ts = 0.f, tss = 0.f;
#pragma unroll
        for (int i = 0; i < 8; i++) { ts += sb[i]; tss += sb2[i]; }
        float mu  = ts  * (1.0f / DD);
        float var = tss * (1.0f / DD) - mu * mu;
        stats[0] = mu;
        stats[1] = rsqrtf(var + 1e-5f);
    }
    __syncthreads();
    float mu = stats[0], rs = stats[1];
    int c = tid * 4;
    float4 gg = *(const float4*)(gam + c);
    float4 bb = *(const float4*)(bet + c);
    float vals[4];
    vals[0] = to_tf32((v.x - mu) * rs * gg.x + bb.x);
    vals[1] = to_tf32((v.y - mu) * rs * gg.y + bb.y);
    vals[2] = to_tf32((v.z - mu) * rs * gg.z + bb.z);
    vals[3] = to_tf32((v.w - mu) * rs * gg.w + bb.w);
    int base = c & ~7, o8 = c & 7;    // o8 = 0 or 4
    float* op = out + (size_t)row * DD + base;
#pragma unroll
    for (int i = 0; i < 4; i++)
        op[pperm(o8 + i)] = vals[i];
}

// =================== bf16 3-pass GEMM (qkv only; 3-stage pipeline) =========
#define OFF_AH 0
#define OFF_AL 8192
#define OFF_BH 16384
#define OFF_BL 24576
#define STAGE  32768
#define NSTAGE 3
#define TCG_SMEM (NSTAGE * STAGE)

__device__ __forceinline__ uint32_t swz32(int row, int chunk) {
    return (uint32_t)(row * 64 + (((chunk ^ (row >> 1)) & 3) << 4));
}

__device__ __forceinline__ void cp_stage(uint32_t sbase,
                                         const __nv_bfloat16* __restrict__ Ahi,
                                         const __nv_bfloat16* __restrict__ Alo,
                                         const __nv_bfloat16* __restrict__ Bhi,
                                         const __nv_bfloat16* __restrict__ Blo,
                                         int am0, int bn0, int k0, int ldk, int tid)
{
#pragma unroll
    for (int j = 0; j < 2; j++) {
        int v = tid + (j << 8);
        int r = v >> 2, c = v & 3;
        uint32_t so = swz32(r, c);
        size_t goA = (size_t)(am0 + r) * ldk + k0 + c * 8;
        size_t goB = (size_t)(bn0 + r) * ldk + k0 + c * 8;
        cp_async16(sbase + OFF_AH + so, Ahi + goA);
        cp_async16(sbase + OFF_AL + so, Alo + goA);
        cp_async16(sbase + OFF_BH + so, Bhi + goB);
        cp_async16(sbase + OFF_BL + so, Blo + goB);
    }
}

__global__ __launch_bounds__(256, 2)
void tc_gemm_bf(const __nv_bfloat16* __restrict__ Ahi, const __nv_bfloat16* __restrict__ Alo,
                const __nv_bfloat16* __restrict__ Bhi, const __nv_bfloat16* __restrict__ Blo,
                const float* __restrict__ bias,
                __nv_bfloat16* __restrict__ Chi, __nv_bfloat16* __restrict__ Clo,
                int M, int N, int K)
{
    extern __shared__ __align__(128) char smc[];
    uint32_t sb = smem_u32(smc);
    int tid = threadIdx.x, wid = tid >> 5, lane = tid & 31;
    int warp_m = wid >> 1, warp_n = wid & 1;
    int bn = blockIdx.x, bm = blockIdx.y;
    int am0 = bm * 128, bn0 = bn * 128;

    float acc[2][8][4];
#pragma unroll
    for (int mi = 0; mi < 2; mi++)
#pragma unroll
        for (int ni = 0; ni < 8; ni++)
#pragma unroll
            for (int q = 0; q < 4; q++) acc[mi][ni][q] = 0.f;

    int lrA = (lane & 7) + ((lane >> 3) & 1) * 8;
    uint32_t cAoff = (uint32_t)((lane >> 4) << 4);
    uint32_t aB[2], aX[2];
#pragma unroll
    for (int mi = 0; mi < 2; mi++) {
        int row = warp_m * 32 + mi * 16 + lrA;
        aB[mi] = (uint32_t)(row * 64);
        aX[mi] = cAoff ^ (uint32_t)((((row >> 1) & 3)) << 4);
    }
    int lrB = (lane & 7) + ((lane >> 4) & 1) * 8;
    uint32_t cBoff = (uint32_t)(((lane >> 3) & 1) << 4);
    uint32_t bB[4], bX[4];
#pragma unroll
    for (int p = 0; p < 4; p++) {
        int row = warp_n * 64 + p * 16 + lrB;
        bB[p] = (uint32_t)(row * 64);
        bX[p] = cBoff ^ (uint32_t)((((row >> 1) & 3)) << 4);
    }

    int nchunk = K >> 5;
    cp_stage(sb + 0 * STAGE, Ahi, Alo, Bhi, Blo, am0, bn0, 0, K, tid);
    cp_commit();
    cp_stage(sb + 1 * STAGE, Ahi, Alo, Bhi, Blo, am0, bn0, 32, K, tid);
    cp_commit();

    int slot = 0;
    for (int ch = 0; ch < nchunk; ch++) {
        uint32_t st = sb + (uint32_t)slot * STAGE;
        cp_wait<1>();
        __syncthreads();
        int nslot = slot + 2; if (nslot >= NSTAGE) nslot -= NSTAGE;
        if (ch + 2 < nchunk)
            cp_stage(sb + (uint32_t)nslot * STAGE, Ahi, Alo, Bhi, Blo,
                     am0, bn0, (ch + 2) << 5, K, tid);
        cp_commit();

#pragma unroll
        for (int ks = 0; ks < 2; ks++) {
            uint32_t kx = (uint32_t)(ks << 5);
            uint32_t ah[2][4], bh[8][2];
#pragma unroll
            for (int mi = 0; mi < 2; mi++)
                ldsm_x4(ah[mi], st + OFF_AH + aB[mi] + (kx ^ aX[mi]));
#pragma unroll
            for (int p = 0; p < 4; p++) {
                uint32_t r4[4];
                ldsm_x4(r4, st + OFF_BH + bB[p] + (kx ^ bX[p]));
                bh[2 * p][0] = r4[0]; bh[2 * p][1] = r4[1];
                bh[2 * p + 1][0] = r4[2]; bh[2 * p + 1][1] = r4[3];
            }
#pragma unroll
            for (int mi = 0; mi < 2; mi++)
#pragma unroll
                for (int ni = 0; ni < 8; ni++)
                    mma16816(acc[mi][ni], ah[mi], bh[ni]);
            {
                uint32_t al[2][4];
#pragma unroll
                for (int mi = 0; mi < 2; mi++)
                    ldsm_x4(al[mi], st + OFF_AL + aB[mi] + (kx ^ aX[mi]));
#pragma unroll
                for (int mi = 0; mi < 2; mi++)
#pragma unroll
                    for (int ni = 0; ni < 8; ni++)
                        mma16816(acc[mi][ni], al[mi], bh[ni]);
            }
            {
                uint32_t bl[8][2];
#pragma unroll
                for (int p = 0; p < 4; p++) {
                    uint32_t r4[4];
                    ldsm_x4(r4, st + OFF_BL + bB[p] + (kx ^ bX[p]));
                    bl[2 * p][0] = r4[0]; bl[2 * p][1] = r4[1];
                    bl[2 * p + 1][0] = r4[2]; bl[2 * p + 1][1] = r4[3];
                }
#pragma unroll
                for (int mi = 0; mi < 2; mi++)
#pragma unroll
                    for (int ni = 0; ni < 8; ni++)
                        mma16816(acc[mi][ni], ah[mi], bl[ni]);
            }
        }
        slot++; if (slot >= NSTAGE) slot = 0;
    }

    int g = lane >> 2, tig = lane & 3;
#pragma unroll
    for (int mi = 0; mi < 2; mi++) {
#pragma unroll
        for (int half = 0; half < 2; half++) {
            int r = bm * 128 + warp_m * 32 + mi * 16 + g + half * 8;
#pragma unroll
            for (int ni = 0; ni < 8; ni++) {
                int c = bn * 128 + warp_n * 64 + ni * 8 + tig * 2;
                float v0 = acc[mi][ni][half * 2 + 0];
                float v1 = acc[mi][ni][half * 2 + 1];
                float2 bv = *(const float2*)(bias + c);
                v0 += bv.x; v1 += bv.y;
                store_hilo2(Chi, Clo, (size_t)r * N + c, v0, v1);
            }
        }
    }
}

// ===== tf32 1-pass GEMM (k-permuted, XOR-swizzled rows, LDS.64 frags) ======
#define TTILEB 8192                 // bytes per 128x16 float tile
#define TSTB   (2 * TTILEB)         // bytes per stage (A + B)
#define TSTF   (TSTB / 4)           // floats per stage
#define TF_SMEM (3 * TSTB)          // 49152 bytes

__device__ __forceinline__ void cp_stage_tf(uint32_t sbase,
                                            const float* __restrict__ A,
                                            const float* __restrict__ Bt,
                                            int am0, int bn0, int k0, int ldk, int tid)
{
#pragma unroll
    for (int j = 0; j < 4; j++) {
        int idx = tid + (j << 8);        // 0..1023
        int tile = idx >> 9;
        int w = idx & 511;
        int r = w >> 2, c = w & 3;       // row, 16B chunk
        uint32_t dst = sbase + (uint32_t)tile * TTILEB
                     + (uint32_t)(r * 64) + (uint32_t)(((c ^ (r & 3)) << 4));
        const float* src = (tile ? Bt + (size_t)(bn0 + r) * ldk : A + (size_t)(am0 + r) * ldk)
                           + k0 + c * 4;
        cp_async16(dst, src);
    }
}

template <int EPI>
__global__ __launch_bounds__(256, 2)
void tf_gemm(const float* __restrict__ A, const float* __restrict__ Bt,
             const float* __restrict__ bias, const float* __restrict__ res,
             float* __restrict__ Cf, int M, int N, int K)
{
    extern __shared__ __align__(128) float smf[];
    int tid = threadIdx.x, wid = tid >> 5, lane = tid & 31;
    int warp_m = wid >> 2, warp_n = wid & 3;     // 2m x 4n
    int g = lane >> 2, tig = lane & 3;
    int bn = blockIdx.x, bm = blockIdx.y;
    int am0 = bm * 128, bn0 = bn * 128;

    float acc[4][4][4];
#pragma unroll
    for (int mi = 0; mi < 4; mi++)
#pragma unroll
        for (int ni = 0; ni < 4; ni++)
#pragma unroll
            for (int q = 0; q < 4; q++) acc[mi][ni][q] = 0.f;

    int nchunk = K >> 4;
    uint32_t sb = smem_u32(smf);
    cp_stage_tf(sb + 0 * TSTB, A, Bt, am0, bn0, 0, K, tid);
    cp_commit();
    cp_stage_tf(sb + 1 * TSTB, A, Bt, am0, bn0, 16, K, tid);
    cp_commit();

    int subo = (tig & 1) * 2;
    int cjt  = tig >> 1;

    int slot = 0;
    for (int ch = 0; ch < nchunk; ch++) {
        cp_wait<1>();
        __syncthreads();
        int nslot = slot + 2; if (nslot >= 3) nslot -= 3;
        if (ch + 2 < nchunk)
            cp_stage_tf(sb + (uint32_t)nslot * TSTB, A, Bt, am0, bn0,
                        (ch + 2) << 4, K, tid);
        cp_commit();

        const float* As = smf + slot * TSTF;
        const float* Bs = As + (TTILEB / 4);

#pragma unroll
        for (int ks = 0; ks < 2; ks++) {
            int cj = ks * 2 + cjt;
            uint32_t a[4][4];
#pragma unroll
            for (int mi = 0; mi < 4; mi++) {
                int r0 = warp_m * 64 + mi * 16 + g;
                int r1 = r0 + 8;
                float2 f0 = *(const float2*)&As[r0 * 16 + ((cj ^ (r0 & 3)) << 2) + subo];
                float2 f1 = *(const float2*)&As[r1 * 16 + ((cj ^ (r1 & 3)) << 2) + subo];
                a[mi][0] = __float_as_uint(f0.x);
                a[mi][1] = __float_as_uint(f1.x);
                a[mi][2] = __float_as_uint(f0.y);
                a[mi][3] = __float_as_uint(f1.y);
            }
            uint32_t b[4][2];
#pragma unroll
            for (int ni = 0; ni < 4; ni++) {
                int rn = warp_n * 32 + ni * 8 + g;
                float2 f = *(const float2*)&Bs[rn * 16 + ((cj ^ (rn & 3)) << 2) + subo];
                b[ni][0] = __float_as_uint(f.x);
                b[ni][1] = __float_as_uint(f.y);
            }
#pragma unroll
            for (int mi = 0; mi < 4; mi++)
#pragma unroll
                for (int ni = 0; ni < 4; ni++)
                    mma_tf32(acc[mi][ni], a[mi], b[ni]);
        }
        slot++; if (slot >= 3) slot = 0;
    }

#pragma unroll
    for (int mi = 0; mi < 4; mi++) {
#pragma unroll
        for (int half = 0; half < 2; half++) {
            int r = bm * 128 + warp_m * 64 + mi * 16 + g + half * 8;
#pragma unroll
            for (int ni = 0; ni < 4; ni++) {
                int c = bn * 128 + warp_n * 32 + ni * 8 + tig * 2;
                float v0 = acc[mi][ni][half * 2 + 0];
                float v1 = acc[mi][ni][half * 2 + 1];
                float2 bv = *(const float2*)(bias + c);
                v0 += bv.x; v1 += bv.y;
                size_t rowb = (size_t)r * N;
                if (EPI == 1) {
                    int cb = c & ~7, j = c & 7;
                    Cf[rowb + cb + pperm(j)]     = to_tf32(gelu_fast(v0));
                    Cf[rowb + cb + pperm(j + 1)] = to_tf32(gelu_fast(v1));
                } else {
                    float2 rv = *(const float2*)(res + rowb + c);
                    v0 += rv.x; v1 += rv.y;
                    *(float2*)(Cf + rowb + c) = make_float2(v0, v1);
                }
            }
        }
    }
}

// ============ Tensor-core causal flash attention (cp.async pipelined) ======
#define AQH 0
#define AQL 8192
#define ASTG 16384
#define SKH 0
#define SKL 8192
#define SVH 16384
#define SVL 24576
#define SSTG 32768
#define ATT_SMEM (ASTG + 3 * SSTG)   // 112 KB

__device__ __forceinline__ void attn_cp_kv(uint32_t stg,
                                           const __nv_bfloat16* __restrict__ qh,
                                           const __nv_bfloat16* __restrict__ ql,
                                           size_t rowbase, int hoff, int tid)
{
#pragma unroll
    for (int j = 0; j < 4; j++) {
        int idx = tid + (j << 7);
        int r = idx >> 3, c = idx & 7;
        uint32_t ad = (uint32_t)(r * 128) + (uint32_t)(((c ^ r) & 7) << 4);
        size_t gK = rowbase + (size_t)r * (3 * DD) + DD + hoff + c * 8;
        size_t gV = rowbase + (size_t)r * (3 * DD) + 2 * DD + hoff + c * 8;
        cp_async16(stg + SKH + ad, qh + gK);
        cp_async16(stg + SKL + ad, ql + gK);
        cp_async16(stg + SVH + ad, qh + gV);
        cp_async16(stg + SVL + ad, ql + gV);
    }
}

__global__ __launch_bounds__(128)
void attn_kernel(const __nv_bfloat16* __restrict__ qkvh,
                 const __nv_bfloat16* __restrict__ qkvl,
                 float* __restrict__ oat)
{
    extern __shared__ __align__(128) char sma[];
    uint32_t sb = smem_u32(sma);
    int qt = (int)gridDim.x - 1 - (int)blockIdx.x;
    int h = blockIdx.y, b = blockIdx.z;
    int tid = threadIdx.x, warp = tid >> 5, lane = tid & 31;
    int q0 = qt * 64;
    int g = lane >> 2, tig = lane & 3;
    int hoff = h * HDIM;

    {
        size_t rowQ = (size_t)(b * SS + q0) * (3 * DD);
#pragma unroll
        for (int j = 0; j < 4; j++) {
            int idx = tid + (j << 7);
            int r = idx >> 3, c = idx & 7;
            uint32_t ad = (uint32_t)(r * 128) + (uint32_t)(((c ^ r) & 7) << 4);
            size_t gQ = rowQ + (size_t)r * (3 * DD) + hoff + c * 8;
            cp_async16(sb + AQH + ad, qkvh + gQ);
            cp_async16(sb + AQL + ad, qkvl + gQ);
        }
        attn_cp_kv(sb + ASTG, qkvh, qkvl, (size_t)(b * SS) * (3 * DD), hoff, tid);
        cp_commit();
        attn_cp_kv(sb + ASTG + SSTG, qkvh, qkvl,
                   (size_t)(b * SS + 64) * (3 * DD), hoff, tid);
        cp_commit();
    }

    int lrA = (lane & 7) + ((lane >> 3) & 1) * 8;
    uint32_t cA = (uint32_t)((lane >> 4) << 4);
    int rowA = warp * 16 + lrA;
    uint32_t aBase = (uint32_t)(rowA * 128);
    uint32_t aMask = (uint32_t)((rowA & 7) << 4);

    int lrB = (lane & 7) + ((lane >> 4) & 1) * 8;
    uint32_t cB = (uint32_t)(((lane >> 3) & 1) << 4);

    int lrV = (lane & 7) + ((lane >> 3) & 1) * 8;
    uint32_t cV = (uint32_t)(((lane >> 4) & 1) << 4);

    float oacc[8][4];
    float mA = -1e30f, mB = -1e30f, lA = 0.f, lB = 0.f;
#pragma unroll
    for (int t = 0; t < 8; t++)
#pragma unroll
        for (int q = 0; q < 4; q++) oacc[t][q] = 0.f;

    int slot = 0;
    for (int kt = 0; kt <= qt; kt++) {
        uint32_t st = sb + ASTG + (uint32_t)slot * SSTG;
        cp_wait<1>();
        __syncthreads();
        int nslot = slot + 2; if (nslot >= 3) nslot -= 3;
        if (kt + 2 <= qt)
            attn_cp_kv(sb + ASTG + (uint32_t)nslot * SSTG, qkvh, qkvl,
                       (size_t)(b * SS + (kt + 2) * 64) * (3 * DD), hoff, tid);
        cp_commit();

        float sacc[8][4];
#pragma unroll
        for (int t = 0; t < 8; t++)
#pragma unroll
            for (int q = 0; q < 4; q++) sacc[t][q] = 0.f;

#pragma unroll
        for (int ks = 0; ks < 4; ks++) {
            uint32_t kx = (uint32_t)(ks * 32);
            uint32_t qh4[4], ql4[4], kh[8][2];
            ldsm_x4(qh4, sb + AQH + aBase + ((kx + cA) ^ aMask));
            ldsm_x4(ql4, sb + AQL + aBase + ((kx + cA) ^ aMask));
#pragma unroll
            for (int p = 0; p < 4; p++) {
                int rowB = p * 16 + lrB;
                uint32_t r4[4];
                ldsm_x4(r4, st + SKH + (uint32_t)(rowB * 128) +
                            ((kx + cB) ^ (uint32_t)((rowB & 7) << 4)));
                kh[2 * p][0] = r4[0]; kh[2 * p][1] = r4[1];
                kh[2 * p + 1][0] = r4[2]; kh[2 * p + 1][1] = r4[3];
            }
#pragma unroll
            for (int t = 0; t < 8; t++) mma16816(sacc[t], qh4, kh[t]);
#pragma unroll
            for (int t = 0; t < 8; t++) mma16816(sacc[t], ql4, kh[t]);
            {
                uint32_t kl[8][2];
#pragma unroll
                for (int p = 0; p < 4; p++) {
                    int rowB = p * 16 + lrB;
                    uint32_t r4[4];
                    ldsm_x4(r4, st + SKL + (uint32_t)(rowB * 128) +
                                ((kx + cB) ^ (uint32_t)((rowB & 7) << 4)));
                    kl[2 * p][0] = r4[0]; kl[2 * p][1] = r4[1];
                    kl[2 * p + 1][0] = r4[2]; kl[2 * p + 1][1] = r4[3];
                }
#pragma unroll
                for (int t = 0; t < 8; t++) mma16816(sacc[t], qh4, kl[t]);
            }
        }

#pragma unroll
        for (int t = 0; t < 8; t++) {
            sacc[t][0] *= 0.125f; sacc[t][1] *= 0.125f;
            sacc[t][2] *= 0.125f; sacc[t][3] *= 0.125f;
        }

        if (kt == qt) {
            int qlocA = warp * 16 + g, qlocB = qlocA + 8;
#pragma unroll
            for (int t = 0; t < 8; t++) {
                int k0c = t * 8 + tig * 2;
                if (k0c > qlocA)     sacc[t][0] = -1e30f;
                if (k0c + 1 > qlocA) sacc[t][1] = -1e30f;
                if (k0c > qlocB)     sacc[t][2] = -1e30f;
                if (k0c + 1 > qlocB) sacc[t][3] = -1e30f;
            }
        }

        float maA = -1e30f, maB = -1e30f;
#pragma unroll
        for (int t = 0; t < 8; t++) {
            maA = fmaxf(maA, fmaxf(sacc[t][0], sacc[t][1]));
            maB = fmaxf(maB, fmaxf(sacc[t][2], sacc[t][3]));
        }
        maA = fmaxf(maA, __shfl_xor_sync(0xffffffffu, maA, 1));
        maA = fmaxf(maA, __shfl_xor_sync(0xffffffffu, maA, 2));
        maB = fmaxf(maB, __shfl_xor_sync(0xffffffffu, maB, 1));
        maB = fmaxf(maB, __shfl_xor_sync(0xffffffffu, maB, 2));
        float nmA = fmaxf(mA, maA), nmB = fmaxf(mB, maB);
        float corrA = fexp(mA - nmA), corrB = fexp(mB - nmB);
        mA = nmA; mB = nmB;
        float sumA = 0.f, sumB = 0.f;
#pragma unroll
        for (int t = 0; t < 8; t++) {
            sacc[t][0] = fexp(sacc[t][0] - nmA);
            sacc[t][1] = fexp(sacc[t][1] - nmA);
            sacc[t][2] = fexp(sacc[t][2] - nmB);
            sacc[t][3] = fexp(sacc[t][3] - nmB);
            sumA += sacc[t][0] + sacc[t][1];
            sumB += sacc[t][2] + sacc[t][3];
        }
        sumA += __shfl_xor_sync(0xffffffffu, sumA, 1);
        sumA += __shfl_xor_sync(0xffffffffu, sumA, 2);
        sumB += __shfl_xor_sync(0xffffffffu, sumB, 1);
        sumB += __shfl_xor_sync(0xffffffffu, sumB, 2);
        lA = lA * corrA + sumA;
        lB = lB * corrB + sumB;
#pragma unroll
        for (int t = 0; t < 8; t++) {
            oacc[t][0] *= corrA; oacc[t][1] *= corrA;
            oacc[t][2] *= corrB; oacc[t][3] *= corrB;
        }

        uint32_t ph[4][4], pl[4][4];
#pragma unroll
        for (int p = 0; p < 4; p++) {
#pragma unroll
            for (int q = 0; q < 4; q++) {
                int t = 2 * p + (q >> 1);
                float a = sacc[t][(q & 1) * 2 + 0];
                float bv = sacc[t][(q & 1) * 2 + 1];
                __nv_bfloat16 ah2 = __float2bfloat16(a), bh2 = __float2bfloat16(bv);
                __nv_bfloat162 th = __halves2bfloat162(ah2, bh2);
                ph[p][q] = *(uint32_t*)&th;
                __nv_bfloat162 tl = __halves2bfloat162(
                    __float2bfloat16(a - __bfloat162float(ah2)),
                    __float2bfloat16(bv - __bfloat162float(bh2)));
                pl[p][q] = *(uint32_t*)&tl;
            }
        }

#pragma unroll
        for (int ks = 0; ks < 4; ks++) {
            int rowV = ks * 16 + lrV;
            uint32_t vMask = (uint32_t)((rowV & 7) << 4);
            uint32_t vbh[8][2], vbl[8][2];
#pragma unroll
            for (int j = 0; j < 4; j++) {
                uint32_t cb = (uint32_t)(j * 32) + cV;
                uint32_t r4[4];
                ldsm_x4_t(r4, st + SVH + (uint32_t)(rowV * 128) + (cb ^ vMask));
                vbh[2 * j][0] = r4[0]; vbh[2 * j][1] = r4[1];
                vbh[2 * j + 1][0] = r4[2]; vbh[2 * j + 1][1] = r4[3];
            }
#pragma unroll
            for (int j = 0; j < 4; j++) {
                uint32_t cb = (uint32_t)(j * 32) + cV;
                uint32_t r4[4];
                ldsm_x4_t(r4, st + SVL + (uint32_t)(rowV * 128) + (cb ^ vMask));
                vbl[2 * j][0] = r4[0]; vbl[2 * j][1] = r4[1];
                vbl[2 * j + 1][0] = r4[2]; vbl[2 * j + 1][1] = r4[3];
            }
#pragma unroll
            for (int t = 0; t < 8; t++) mma16816(oacc[t], ph[ks], vbh[t]);
#pragma unroll
            for (int t = 0; t < 8; t++) mma16816(oacc[t], pl[ks], vbh[t]);
#pragma unroll
            for (int t = 0; t < 8; t++) mma16816(oacc[t], ph[ks], vbl[t]);
        }
        slot++; if (slot >= 3) slot = 0;
    }

    // ---- normalize + k-permuted write (feeds o-proj tf32 GEMM) ----
    float invA = 1.0f / lA, invB = 1.0f / lB;
    int rowAg = b * SS + q0 + warp * 16 + g;
    int rowBg = rowAg + 8;
#pragma unroll
    for (int t = 0; t < 8; t++) {
        int gbase = h * HDIM + t * 8;
        int j0 = tig * 2;
        float* pA = oat + (size_t)rowAg * DD + gbase;
        float* pB = oat + (size_t)rowBg * DD + gbase;
        pA[pperm(j0)]     = to_tf32(oacc[t][0] * invA);
        pA[pperm(j0 + 1)] = to_tf32(oacc[t][1] * invA);
        pB[pperm(j0)]     = to_tf32(oacc[t][2] * invB);
        pB[pperm(j0 + 1)] = to_tf32(oacc[t][3] * invB);
    }
}

// ---------------- launch (fork-join graph) ---------------------------------
extern "C" void kernel_launch(void* const* d_in, const int* in_sizes, int n_in,
                              void* d_out, int out_size)
{
    const float* x    = (const float*)d_in[0];
    const float* pos  = (const float*)d_in[1];
    const float* ln1g = (const float*)d_in[2];
    const float* ln1b = (const float*)d_in[3];
    const float* wqkv = (const float*)d_in[4];
    const float* bqkv = (const float*)d_in[5];
    const float* wo   = (const float*)d_in[6];
    const float* bo   = (const float*)d_in[7];
    const float* ln2g = (const float*)d_in[8];
    const float* ln2b = (const float*)d_in[9];
    const float* wfc  = (const float*)d_in[10];
    const float* bfc  = (const float*)d_in[11];
    const float* wpr  = (const float*)d_in[12];
    const float* bpr  = (const float*)d_in[13];
    float* out = (float*)d_out;

    __nv_bfloat16 *p_h_hi, *p_h_lo, *p_qkvh, *p_qkvl, *p_wqkv_hi, *p_wqkv_lo;
    float *p_at, *p_x2, *p_m, *p_ff, *p_woT, *p_wfcT, *p_wprT;
    cudaGetSymbolAddress((void**)&p_h_hi, g_h_hi);   cudaGetSymbolAddress((void**)&p_h_lo, g_h_lo);
    cudaGetSymbolAddress((void**)&p_qkvh, g_qkvh);   cudaGetSymbolAddress((void**)&p_qkvl, g_qkvl);
    cudaGetSymbolAddress((void**)&p_at, g_at);
    cudaGetSymbolAddress((void**)&p_x2, g_x2);
    cudaGetSymbolAddress((void**)&p_m, g_m);
    cudaGetSymbolAddress((void**)&p_ff, g_ff);
    cudaGetSymbolAddress((void**)&p_wqkv_hi, g_wqkv_hi); cudaGetSymbolAddress((void**)&p_wqkv_lo, g_wqkv_lo);
    cudaGetSymbolAddress((void**)&p_woT, g_woT);
    cudaGetSymbolAddress((void**)&p_wfcT, g_wfcT);
    cudaGetSymbolAddress((void**)&p_wprT, g_wprT);

    cudaFuncSetAttribute(tc_gemm_bf, cudaFuncAttributeMaxDynamicSharedMemorySize, TCG_SMEM);
    cudaFuncSetAttribute(tf_gemm<1>, cudaFuncAttributeMaxDynamicSharedMemorySize, TF_SMEM);
    cudaFuncSetAttribute(tf_gemm<2>, cudaFuncAttributeMaxDynamicSharedMemorySize, TF_SMEM);
    cudaFuncSetAttribute(attn_kernel, cudaFuncAttributeMaxDynamicSharedMemorySize, ATT_SMEM);

    dim3 tb(32, 8);

    // --- fork: s1 = qkv weight split, s2 = tf32 weight transposes ----------
    cudaEventRecord(g_ev0, 0);
    cudaStreamWaitEvent(g_s1, g_ev0, 0);
    cudaStreamWaitEvent(g_s2, g_ev0, 0);

    wsplit_t<<<dim3(3 * DD / 32, DD / 32), tb, 0, g_s1>>>(wqkv, p_wqkv_hi, p_wqkv_lo, DD, 3 * DD);
    wtrans<<<dim3(DD / 32, DD / 32), tb, 0, g_s2>>>(wo, p_woT, DD, DD);
    wtrans<<<dim3(DFFN / 32, DD / 32), tb, 0, g_s2>>>(wfc, p_wfcT, DD, DFFN);
    wtrans<<<dim3(DD / 32, DFFN / 32), tb, 0, g_s2>>>(wpr, p_wprT, DFFN, DD);

    // main stream: LN1 (independent of weight prep)
    ln_bf<<<ROWS, 256>>>(x, ln1g, ln1b, pos, p_h_hi, p_h_lo);

    // join s1 before qkv GEMM (needs wqkv split)
    cudaEventRecord(g_ev1, g_s1);
    cudaStreamWaitEvent(0, g_ev1, 0);

    // 2) qkv = h @ w_qkv + b_qkv -> bf16 hi/lo (3-pass, accuracy-critical)
    tc_gemm_bf<<<dim3(3 * DD / 128, ROWS / 128), 256, TCG_SMEM>>>(
        p_h_hi, p_h_lo, p_wqkv_hi, p_wqkv_lo, bqkv,
        p_qkvh, p_qkvl, ROWS, 3 * DD, DD);

    // 3) causal attention -> tf32 fp32, k-permuted (wtrans hides under 2+3)
    attn_kernel<<<dim3(SS / 64, HH, BB), 128, ATT_SMEM>>>(p_qkvh, p_qkvl, p_at);

    // join s2 before o-proj (needs woT/wfcT/wprT)
    cudaEventRecord(g_ev2, g_s2);
    cudaStreamWaitEvent(0, g_ev2, 0);

    // 4) x2 = x + attn @ w_o + b_o (tf32)
    tf_gemm<2><<<dim3(DD / 128, ROWS / 128), 256, TF_SMEM>>>(
        p_at, p_woT, bo, x, p_x2, ROWS, DD, DD);

    // 5) m = LN2(x2) -> tf32 fp32, k-permuted
    ln_tf<<<ROWS, 256>>>(p_x2, ln2g, ln2b, p_m);

    // 6) ff = gelu(m @ w_fc + b_fc) (tf32) -> tf32 fp32, k-permuted
    tf_gemm<1><<<dim3(DFFN / 128, ROWS / 128), 256, TF_SMEM>>>(
        p_m, p_wfcT, bfc, nullptr, p_ff, ROWS, DFFN, DD);

    // 7) out = x2 + ff @ w_proj + b_proj (tf32)
    tf_gemm<2><<<dim3(DD / 128, ROWS / 128), 256, TF_SMEM>>>(
        p_ff, p_wprT, bpr, p_x2, out, ROWS, DD, DFFN);
}

// round 16
// speedup vs baseline: 1.0773x; 1.0400x over previous
#include <cuda_runtime.h>
#include <cuda_bf16.h>
#include <math.h>
#include <stdint.h>

// Problem constants
#define BB   2
#define SS   2048
#define DD   1024
#define HH   16
#define HDIM 64
#define DFFN 4096
#define ROWS (BB * SS)   // 4096

// -------- scratch (static device globals; no allocation) --------
__device__ __align__(16) float         g_h[ROWS * DD];           // tf32, k-permuted
__device__ __align__(16) __nv_bfloat16 g_qkvh[ROWS * 3 * DD], g_qkvl[ROWS * 3 * DD];
__device__ __align__(16) float         g_at[ROWS * DD];          // tf32, k-permuted
__device__ __align__(16) float         g_x2[ROWS * DD];
__device__ __align__(16) float         g_m[ROWS * DD];           // tf32, k-permuted
__device__ __align__(16) float         g_ff[ROWS * DFFN];        // tf32, k-permuted
__device__ __align__(16) float         g_wqkvT[3 * DD * DD];     // k-permuted
__device__ __align__(16) float         g_woT[DD * DD];           // k-permuted
__device__ __align__(16) float         g_wfcT[DFFN * DD];        // k-permuted
__device__ __align__(16) float         g_wprT[DD * DFFN];        // k-permuted

// -------- side streams/events for graph fork-join (host objects only) ------
static cudaStream_t g_s1 = nullptr, g_s2 = nullptr;
static cudaEvent_t  g_ev0 = nullptr, g_ev1 = nullptr, g_ev2 = nullptr;
struct _StreamInit {
    _StreamInit() {
        cudaStreamCreateWithFlags(&g_s1, cudaStreamNonBlocking);
        cudaStreamCreateWithFlags(&g_s2, cudaStreamNonBlocking);
        cudaEventCreateWithFlags(&g_ev0, cudaEventDisableTiming);
        cudaEventCreateWithFlags(&g_ev1, cudaEventDisableTiming);
        cudaEventCreateWithFlags(&g_ev2, cudaEventDisableTiming);
    }
};
static _StreamInit _stream_init_once;

// ======================= portable PTX helpers ==============================
__device__ __forceinline__ uint32_t smem_u32(const void* p) {
    uint32_t a;
    asm("{ .reg .u64 t; cvta.to.shared.u64 t, %1; cvt.u32.u64 %0, t; }" : "=r"(a) : "l"(p));
    return a;
}

__device__ __forceinline__ void cp_async16(uint32_t saddr, const void* gaddr) {
    asm volatile("cp.async.cg.shared.global [%0], [%1], 16;" :: "r"(saddr), "l"(gaddr));
}
__device__ __forceinline__ void cp_commit() {
    asm volatile("cp.async.commit_group;" ::: "memory");
}
template <int N>
__device__ __forceinline__ void cp_wait() {
    asm volatile("cp.async.wait_group %0;" :: "n"(N) : "memory");
}

__device__ __forceinline__ void ldsm_x4(uint32_t* r, uint32_t addr) {
    asm volatile("ldmatrix.sync.aligned.m8n8.x4.shared.b16 {%0,%1,%2,%3}, [%4];"
        : "=r"(r[0]), "=r"(r[1]), "=r"(r[2]), "=r"(r[3]) : "r"(addr));
}
__device__ __forceinline__ void ldsm_x4_t(uint32_t* r, uint32_t addr) {
    asm volatile("ldmatrix.sync.aligned.m8n8.x4.trans.shared.b16 {%0,%1,%2,%3}, [%4];"
        : "=r"(r[0]), "=r"(r[1]), "=r"(r[2]), "=r"(r[3]) : "r"(addr));
}

__device__ __forceinline__ void mma16816(float* c, const uint32_t* a, const uint32_t* b) {
    asm volatile(
        "mma.sync.aligned.m16n8k16.row.col.f32.bf16.bf16.f32 "
        "{%0,%1,%2,%3}, {%4,%5,%6,%7}, {%8,%9}, {%0,%1,%2,%3};"
        : "+f"(c[0]), "+f"(c[1]), "+f"(c[2]), "+f"(c[3])
        : "r"(a[0]), "r"(a[1]), "r"(a[2]), "r"(a[3]), "r"(b[0]), "r"(b[1]));
}

__device__ __forceinline__ void mma_tf32(float* c, const uint32_t* a, const uint32_t* b) {
    asm volatile(
        "mma.sync.aligned.m16n8k8.row.col.f32.tf32.tf32.f32 "
        "{%0,%1,%2,%3}, {%4,%5,%6,%7}, {%8,%9}, {%0,%1,%2,%3};"
        : "+f"(c[0]), "+f"(c[1]), "+f"(c[2]), "+f"(c[3])
        : "r"(a[0]), "r"(a[1]), "r"(a[2]), "r"(a[3]), "r"(b[0]), "r"(b[1]));
}

__device__ __forceinline__ float to_tf32(float x) {
    uint32_t o;
    asm("cvt.rna.tf32.f32 %0, %1;" : "=r"(o) : "f"(x));
    return __uint_as_float(o);
}

// k-permutation within 8-groups: position 2t holds k=t, position 2t+1 holds k=t+4
__device__ __forceinline__ int pperm(int j) { return ((j & 3) << 1) | (j >> 2); }

// ======================= small math helpers ================================
__device__ __forceinline__ float fexp(float x) {
    float y = fminf(fmaxf(x * 1.4426950408889634f, -126.0f), 126.0f);
    float z = y + 12582912.0f;
    int   n = __float_as_int(z) - 0x4B400000;
    float f = y - (z - 12582912.0f);
    float p = 0.0013333558146f;
    p = fmaf(p, f, 0.0096181291076f);
    p = fmaf(p, f, 0.0555041086648f);
    p = fmaf(p, f, 0.2402265069591f);
    p = fmaf(p, f, 0.6931471805599f);
    p = fmaf(p, f, 1.0f);
    return p * __int_as_float((n + 127) << 23);
}

// gelu (tanh approx) via exact identity: 0.5x(1+tanh z) = x / (1 + e^{-2z})
__device__ __forceinline__ float gelu_fast(float x) {
    float x2 = x * x;
    float z2 = 1.5957691216057308f * fmaf(0.044715f * x2, x, x);  // 2z
    float e = fexp(-z2);
    return __fdividef(x, 1.0f + e);
}

__device__ __forceinline__ void store_hilo2(__nv_bfloat16* oh, __nv_bfloat16* ol,
                                            size_t idx, float a, float b)
{
    __nv_bfloat16 h0 = __float2bfloat16(a), h1 = __float2bfloat16(b);
    float l0 = a - __bfloat162float(h0), l1 = b - __bfloat162float(h1);
    *(__nv_bfloat162*)(oh + idx) = __halves2bfloat162(h0, h1);
    *(__nv_bfloat162*)(ol + idx) = __halves2bfloat162(__float2bfloat16(l0), __float2bfloat16(l1));
}

// ============ weight transpose + tf32 round, k-permuted ====================
__global__ void wtrans(const float* __restrict__ W, float* __restrict__ T, int K, int N)
{
    __shared__ float t[32][33];
    int bx = blockIdx.x, by = blockIdx.y;
    int x = threadIdx.x, y = threadIdx.y;
#pragma unroll
    for (int i = 0; i < 32; i += 8)
        t[y + i][x] = W[(size_t)(by * 32 + y + i) * N + bx * 32 + x];
    __syncthreads();
    int kp = by * 32 + (x & ~7) + pperm(x & 7);   // permuted k index
#pragma unroll
    for (int i = 0; i < 32; i += 8)
        T[(size_t)(bx * 32 + y + i) * K + kp] = to_tf32(t[x][y + i]);
}

// -------- LayerNorm (+opt pos) -> tf32-rounded fp32, k-permuted ------------
__global__ void ln_tf(const float* __restrict__ x,
                      const float* __restrict__ gam,
                      const float* __restrict__ bet,
                      const float* __restrict__ pos,
                      float* __restrict__ out)
{
    int row = blockIdx.x;
    int tid = threadIdx.x;
    const float4* xr = (const float4*)(x + (size_t)row * DD);
    float4 v = xr[tid];
    float s  = v.x + v.y + v.z + v.w;
    float ss = v.x * v.x + v.y * v.y + v.z * v.z + v.w * v.w;
#pragma unroll
    for (int o = 16; o > 0; o >>= 1) {
        s  += __shfl_xor_sync(0xffffffffu, s,  o);
        ss += __shfl_xor_sync(0xffffffffu, ss, o);
    }
    __shared__ float sb[8], sb2[8], stats[2];
    int wid = tid >> 5, lane = tid & 31;
    if (lane == 0) { sb[wid] = s; sb2[wid] = ss; }
    __syncthreads();
    if (tid == 0) {
        float ts = 0.f, tss = 0.f;
#pragma unroll
        for (int i = 0; i < 8; i++) { ts += sb[i]; tss += sb2[i]; }
        float mu  = ts  * (1.0f / DD);
        float var = tss * (1.0f / DD) - mu * mu;
        stats[0] = mu;
        stats[1] = rsqrtf(var + 1e-5f);
    }
    __syncthreads();
    float mu = stats[0], rs = stats[1];
    int c = tid * 4;
    float4 gg = *(const float4*)(gam + c);
    float4 bb = *(const float4*)(bet + c);
    float vals[4];
    vals[0] = (v.x - mu) * rs * gg.x + bb.x;
    vals[1] = (v.y - mu) * rs * gg.y + bb.y;
    vals[2] = (v.z - mu) * rs * gg.z + bb.z;
    vals[3] = (v.w - mu) * rs * gg.w + bb.w;
    if (pos) {
        int srow = row % SS;
        float4 p = *(const float4*)(pos + (size_t)srow * DD + c);
        vals[0] += p.x; vals[1] += p.y; vals[2] += p.z; vals[3] += p.w;
    }
    int base = c & ~7, o8 = c & 7;
    float* op = out + (size_t)row * DD + base;
#pragma unroll
    for (int i = 0; i < 4; i++)
        op[pperm(o8 + i)] = to_tf32(vals[i]);
}

// ===== tf32 1-pass GEMM (k-permuted, XOR-swizzled rows, LDS.64 frags) ======
// Tiles: 128 rows x 16 floats (64B rows), chunk c of row r at (c ^ (r&3)).
// 128x128 CTA, 256 thr (8 warps 2m x 4n, 64x32 warp tile), K-chunks of 16.
// EPI: 1 = gelu(+bias) -> tf32 fp32 k-permuted ; 2 = +bias+res -> fp32 ;
//      3 = +bias -> bf16 hi/lo (qkv)
#define TTILEB 8192                 // bytes per 128x16 float tile
#define TSTB   (2 * TTILEB)         // bytes per stage (A + B)
#define TSTF   (TSTB / 4)           // floats per stage
#define TF_SMEM (3 * TSTB)          // 49152 bytes

__device__ __forceinline__ void cp_stage_tf(uint32_t sbase,
                                            const float* __restrict__ A,
                                            const float* __restrict__ Bt,
                                            int am0, int bn0, int k0, int ldk, int tid)
{
#pragma unroll
    for (int j = 0; j < 4; j++) {
        int idx = tid + (j << 8);        // 0..1023
        int tile = idx >> 9;
        int w = idx & 511;
        int r = w >> 2, c = w & 3;       // row, 16B chunk
        uint32_t dst = sbase + (uint32_t)tile * TTILEB
                     + (uint32_t)(r * 64) + (uint32_t)(((c ^ (r & 3)) << 4));
        const float* src = (tile ? Bt + (size_t)(bn0 + r) * ldk : A + (size_t)(am0 + r) * ldk)
                           + k0 + c * 4;
        cp_async16(dst, src);
    }
}

template <int EPI>
__global__ __launch_bounds__(256, 2)
void tf_gemm(const float* __restrict__ A, const float* __restrict__ Bt,
             const float* __restrict__ bias, const float* __restrict__ res,
             float* __restrict__ Cf, __nv_bfloat16* __restrict__ Chi,
             __nv_bfloat16* __restrict__ Clo, int M, int N, int K)
{
    extern __shared__ __align__(128) float smf[];
    int tid = threadIdx.x, wid = tid >> 5, lane = tid & 31;
    int warp_m = wid >> 2, warp_n = wid & 3;     // 2m x 4n
    int g = lane >> 2, tig = lane & 3;
    int bn = blockIdx.x, bm = blockIdx.y;
    int am0 = bm * 128, bn0 = bn * 128;

    float acc[4][4][4];
#pragma unroll
    for (int mi = 0; mi < 4; mi++)
#pragma unroll
        for (int ni = 0; ni < 4; ni++)
#pragma unroll
            for (int q = 0; q < 4; q++) acc[mi][ni][q] = 0.f;

    int nchunk = K >> 4;
    uint32_t sb = smem_u32(smf);
    cp_stage_tf(sb + 0 * TSTB, A, Bt, am0, bn0, 0, K, tid);
    cp_commit();
    cp_stage_tf(sb + 1 * TSTB, A, Bt, am0, bn0, 16, K, tid);
    cp_commit();

    int subo = (tig & 1) * 2;
    int cjt  = tig >> 1;

    int slot = 0;
    for (int ch = 0; ch < nchunk; ch++) {
        cp_wait<1>();
        __syncthreads();
        int nslot = slot + 2; if (nslot >= 3) nslot -= 3;
        if (ch + 2 < nchunk)
            cp_stage_tf(sb + (uint32_t)nslot * TSTB, A, Bt, am0, bn0,
                        (ch + 2) << 4, K, tid);
        cp_commit();

        const float* As = smf + slot * TSTF;
        const float* Bs = As + (TTILEB / 4);

#pragma unroll
        for (int ks = 0; ks < 2; ks++) {
            int cj = ks * 2 + cjt;
            uint32_t a[4][4];
#pragma unroll
            for (int mi = 0; mi < 4; mi++) {
                int r0 = warp_m * 64 + mi * 16 + g;
                int r1 = r0 + 8;
                float2 f0 = *(const float2*)&As[r0 * 16 + ((cj ^ (r0 & 3)) << 2) + subo];
                float2 f1 = *(const float2*)&As[r1 * 16 + ((cj ^ (r1 & 3)) << 2) + subo];
                a[mi][0] = __float_as_uint(f0.x);
                a[mi][1] = __float_as_uint(f1.x);
                a[mi][2] = __float_as_uint(f0.y);
                a[mi][3] = __float_as_uint(f1.y);
            }
            uint32_t b[4][2];
#pragma unroll
            for (int ni = 0; ni < 4; ni++) {
                int rn = warp_n * 32 + ni * 8 + g;
                float2 f = *(const float2*)&Bs[rn * 16 + ((cj ^ (rn & 3)) << 2) + subo];
                b[ni][0] = __float_as_uint(f.x);
                b[ni][1] = __float_as_uint(f.y);
            }
#pragma unroll
            for (int mi = 0; mi < 4; mi++)
#pragma unroll
                for (int ni = 0; ni < 4; ni++)
                    mma_tf32(acc[mi][ni], a[mi], b[ni]);
        }
        slot++; if (slot >= 3) slot = 0;
    }

#pragma unroll
    for (int mi = 0; mi < 4; mi++) {
#pragma unroll
        for (int half = 0; half < 2; half++) {
            int r = bm * 128 + warp_m * 64 + mi * 16 + g + half * 8;
#pragma unroll
            for (int ni = 0; ni < 4; ni++) {
                int c = bn * 128 + warp_n * 32 + ni * 8 + tig * 2;
                float v0 = acc[mi][ni][half * 2 + 0];
                float v1 = acc[mi][ni][half * 2 + 1];
                float2 bv = *(const float2*)(bias + c);
                v0 += bv.x; v1 += bv.y;
                size_t rowb = (size_t)r * N;
                if (EPI == 1) {
                    int cb = c & ~7, j = c & 7;
                    Cf[rowb + cb + pperm(j)]     = to_tf32(gelu_fast(v0));
                    Cf[rowb + cb + pperm(j + 1)] = to_tf32(gelu_fast(v1));
                } else if (EPI == 3) {
                    store_hilo2(Chi, Clo, rowb + c, v0, v1);
                } else {
                    float2 rv = *(const float2*)(res + rowb + c);
                    v0 += rv.x; v1 += rv.y;
                    *(float2*)(Cf + rowb + c) = make_float2(v0, v1);
                }
            }
        }
    }
}

// ============ Tensor-core causal flash attention (cp.async pipelined) ======
#define AQH 0
#define AQL 8192
#define ASTG 16384
#define SKH 0
#define SKL 8192
#define SVH 16384
#define SVL 24576
#define SSTG 32768
#define ATT_SMEM (ASTG + 3 * SSTG)   // 112 KB

__device__ __forceinline__ void attn_cp_kv(uint32_t stg,
                                           const __nv_bfloat16* __restrict__ qh,
                                           const __nv_bfloat16* __restrict__ ql,
                                           size_t rowbase, int hoff, int tid)
{
#pragma unroll
    for (int j = 0; j < 4; j++) {
        int idx = tid + (j << 7);
        int r = idx >> 3, c = idx & 7;
        uint32_t ad = (uint32_t)(r * 128) + (uint32_t)(((c ^ r) & 7) << 4);
        size_t gK = rowbase + (size_t)r * (3 * DD) + DD + hoff + c * 8;
        size_t gV = rowbase + (size_t)r * (3 * DD) + 2 * DD + hoff + c * 8;
        cp_async16(stg + SKH + ad, qh + gK);
        cp_async16(stg + SKL + ad, ql + gK);
        cp_async16(stg + SVH + ad, qh + gV);
        cp_async16(stg + SVL + ad, ql + gV);
    }
}

__global__ __launch_bounds__(128)
void attn_kernel(const __nv_bfloat16* __restrict__ qkvh,
                 const __nv_bfloat16* __restrict__ qkvl,
                 float* __restrict__ oat)
{
    extern __shared__ __align__(128) char sma[];
    uint32_t sb = smem_u32(sma);
    int qt = (int)gridDim.x - 1 - (int)blockIdx.x;
    int h = blockIdx.y, b = blockIdx.z;
    int tid = threadIdx.x, warp = tid >> 5, lane = tid & 31;
    int q0 = qt * 64;
    int g = lane >> 2, tig = lane & 3;
    int hoff = h * HDIM;

    {
        size_t rowQ = (size_t)(b * SS + q0) * (3 * DD);
#pragma unroll
        for (int j = 0; j < 4; j++) {
            int idx = tid + (j << 7);
            int r = idx >> 3, c = idx & 7;
            uint32_t ad = (uint32_t)(r * 128) + (uint32_t)(((c ^ r) & 7) << 4);
            size_t gQ = rowQ + (size_t)r * (3 * DD) + hoff + c * 8;
            cp_async16(sb + AQH + ad, qkvh + gQ);
            cp_async16(sb + AQL + ad, qkvl + gQ);
        }
        attn_cp_kv(sb + ASTG, qkvh, qkvl, (size_t)(b * SS) * (3 * DD), hoff, tid);
        cp_commit();
        attn_cp_kv(sb + ASTG + SSTG, qkvh, qkvl,
                   (size_t)(b * SS + 64) * (3 * DD), hoff, tid);
        cp_commit();
    }

    int lrA = (lane & 7) + ((lane >> 3) & 1) * 8;
    uint32_t cA = (uint32_t)((lane >> 4) << 4);
    int rowA = warp * 16 + lrA;
    uint32_t aBase = (uint32_t)(rowA * 128);
    uint32_t aMask = (uint32_t)((rowA & 7) << 4);

    int lrB = (lane & 7) + ((lane >> 4) & 1) * 8;
    uint32_t cB = (uint32_t)(((lane >> 3) & 1) << 4);

    int lrV = (lane & 7) + ((lane >> 3) & 1) * 8;
    uint32_t cV = (uint32_t)(((lane >> 4) & 1) << 4);

    float oacc[8][4];
    float mA = -1e30f, mB = -1e30f, lA = 0.f, lB = 0.f;
#pragma unroll
    for (int t = 0; t < 8; t++)
#pragma unroll
        for (int q = 0; q < 4; q++) oacc[t][q] = 0.f;

    int slot = 0;
    for (int kt = 0; kt <= qt; kt++) {
        uint32_t st = sb + ASTG + (uint32_t)slot * SSTG;
        cp_wait<1>();
        __syncthreads();
        int nslot = slot + 2; if (nslot >= 3) nslot -= 3;
        if (kt + 2 <= qt)
            attn_cp_kv(sb + ASTG + (uint32_t)nslot * SSTG, qkvh, qkvl,
                       (size_t)(b * SS + (kt + 2) * 64) * (3 * DD), hoff, tid);
        cp_commit();

        float sacc[8][4];
#pragma unroll
        for (int t = 0; t < 8; t++)
#pragma unroll
            for (int q = 0; q < 4; q++) sacc[t][q] = 0.f;

#pragma unroll
        for (int ks = 0; ks < 4; ks++) {
            uint32_t kx = (uint32_t)(ks * 32);
            uint32_t qh4[4], ql4[4], kh[8][2];
            ldsm_x4(qh4, sb + AQH + aBase + ((kx + cA) ^ aMask));
            ldsm_x4(ql4, sb + AQL + aBase + ((kx + cA) ^ aMask));
#pragma unroll
            for (int p = 0; p < 4; p++) {
                int rowB = p * 16 + lrB;
                uint32_t r4[4];
                ldsm_x4(r4, st + SKH + (uint32_t)(rowB * 128) +
                            ((kx + cB) ^ (uint32_t)((rowB & 7) << 4)));
                kh[2 * p][0] = r4[0]; kh[2 * p][1] = r4[1];
                kh[2 * p + 1][0] = r4[2]; kh[2 * p + 1][1] = r4[3];
            }
#pragma unroll
            for (int t = 0; t < 8; t++) mma16816(sacc[t], qh4, kh[t]);
#pragma unroll
            for (int t = 0; t < 8; t++) mma16816(sacc[t], ql4, kh[t]);
            {
                uint32_t kl[8][2];
#pragma unroll
                for (int p = 0; p < 4; p++) {
                    int rowB = p * 16 + lrB;
                    uint32_t r4[4];
                    ldsm_x4(r4, st + SKL + (uint32_t)(rowB * 128) +
                                ((kx + cB) ^ (uint32_t)((rowB & 7) << 4)));
                    kl[2 * p][0] = r4[0]; kl[2 * p][1] = r4[1];
                    kl[2 * p + 1][0] = r4[2]; kl[2 * p + 1][1] = r4[3];
                }
#pragma unroll
                for (int t = 0; t < 8; t++) mma16816(sacc[t], qh4, kl[t]);
            }
        }

#pragma unroll
        for (int t = 0; t < 8; t++) {
            sacc[t][0] *= 0.125f; sacc[t][1] *= 0.125f;
            sacc[t][2] *= 0.125f; sacc[t][3] *= 0.125f;
        }

        if (kt == qt) {
            int qlocA = warp * 16 + g, qlocB = qlocA + 8;
#pragma unroll
            for (int t = 0; t < 8; t++) {
                int k0c = t * 8 + tig * 2;
                if (k0c > qlocA)     sacc[t][0] = -1e30f;
                if (k0c + 1 > qlocA) sacc[t][1] = -1e30f;
                if (k0c > qlocB)     sacc[t][2] = -1e30f;
                if (k0c + 1 > qlocB) sacc[t][3] = -1e30f;
            }
        }

        float maA = -1e30f, maB = -1e30f;
#pragma unroll
        for (int t = 0; t < 8; t++) {
            maA = fmaxf(maA, fmaxf(sacc[t][0], sacc[t][1]));
            maB = fmaxf(maB, fmaxf(sacc[t][2], sacc[t][3]));
        }
        maA = fmaxf(maA, __shfl_xor_sync(0xffffffffu, maA, 1));
        maA = fmaxf(maA, __shfl_xor_sync(0xffffffffu, maA, 2));
        maB = fmaxf(maB, __shfl_xor_sync(0xffffffffu, maB, 1));
        maB = fmaxf(maB, __shfl_xor_sync(0xffffffffu, maB, 2));
        float nmA = fmaxf(mA, maA), nmB = fmaxf(mB, maB);
        float corrA = fexp(mA - nmA), corrB = fexp(mB - nmB);
        mA = nmA; mB = nmB;
        float sumA = 0.f, sumB = 0.f;
#pragma unroll
        for (int t = 0; t < 8; t++) {
            sacc[t][0] = fexp(sacc[t][0] - nmA);
            sacc[t][1] = fexp(sacc[t][1] - nmA);
            sacc[t][2] = fexp(sacc[t][2] - nmB);
            sacc[t][3] = fexp(sacc[t][3] - nmB);
            sumA += sacc[t][0] + sacc[t][1];
            sumB += sacc[t][2] + sacc[t][3];
        }
        sumA += __shfl_xor_sync(0xffffffffu, sumA, 1);
        sumA += __shfl_xor_sync(0xffffffffu, sumA, 2);
        sumB += __shfl_xor_sync(0xffffffffu, sumB, 1);
        sumB += __shfl_xor_sync(0xffffffffu, sumB, 2);
        lA = lA * corrA + sumA;
        lB = lB * corrB + sumB;
#pragma unroll
        for (int t = 0; t < 8; t++) {
            oacc[t][0] *= corrA; oacc[t][1] *= corrA;
            oacc[t][2] *= corrB; oacc[t][3] *= corrB;
        }

        uint32_t ph[4][4], pl[4][4];
#pragma unroll
        for (int p = 0; p < 4; p++) {
#pragma unroll
            for (int q = 0; q < 4; q++) {
                int t = 2 * p + (q >> 1);
                float a = sacc[t][(q & 1) * 2 + 0];
                float bv = sacc[t][(q & 1) * 2 + 1];
                __nv_bfloat16 ah2 = __float2bfloat16(a), bh2 = __float2bfloat16(bv);
                __nv_bfloat162 th = __halves2bfloat162(ah2, bh2);
                ph[p][q] = *(uint32_t*)&th;
                __nv_bfloat162 tl = __halves2bfloat162(
                    __float2bfloat16(a - __bfloat162float(ah2)),
                    __float2bfloat16(bv - __bfloat162float(bh2)));
                pl[p][q] = *(uint32_t*)&tl;
            }
        }

#pragma unroll
        for (int ks = 0; ks < 4; ks++) {
            int rowV = ks * 16 + lrV;
            uint32_t vMask = (uint32_t)((rowV & 7) << 4);
            uint32_t vbh[8][2], vbl[8][2];
#pragma unroll
            for (int j = 0; j < 4; j++) {
                uint32_t cb = (uint32_t)(j * 32) + cV;
                uint32_t r4[4];
                ldsm_x4_t(r4, st + SVH + (uint32_t)(rowV * 128) + (cb ^ vMask));
                vbh[2 * j][0] = r4[0]; vbh[2 * j][1] = r4[1];
                vbh[2 * j + 1][0] = r4[2]; vbh[2 * j + 1][1] = r4[3];
            }
#pragma unroll
            for (int j = 0; j < 4; j++) {
                uint32_t cb = (uint32_t)(j * 32) + cV;
                uint32_t r4[4];
                ldsm_x4_t(r4, st + SVL + (uint32_t)(rowV * 128) + (cb ^ vMask));
                vbl[2 * j][0] = r4[0]; vbl[2 * j][1] = r4[1];
                vbl[2 * j + 1][0] = r4[2]; vbl[2 * j + 1][1] = r4[3];
            }
#pragma unroll
            for (int t = 0; t < 8; t++) mma16816(oacc[t], ph[ks], vbh[t]);
#pragma unroll
            for (int t = 0; t < 8; t++) mma16816(oacc[t], pl[ks], vbh[t]);
#pragma unroll
            for (int t = 0; t < 8; t++) mma16816(oacc[t], ph[ks], vbl[t]);
        }
        slot++; if (slot >= 3) slot = 0;
    }

    // ---- normalize + k-permuted write (feeds o-proj tf32 GEMM) ----
    float invA = 1.0f / lA, invB = 1.0f / lB;
    int rowAg = b * SS + q0 + warp * 16 + g;
    int rowBg = rowAg + 8;
#pragma unroll
    for (int t = 0; t < 8; t++) {
        int gbase = h * HDIM + t * 8;
        int j0 = tig * 2;
        float* pA = oat + (size_t)rowAg * DD + gbase;
        float* pB = oat + (size_t)rowBg * DD + gbase;
        pA[pperm(j0)]     = to_tf32(oacc[t][0] * invA);
        pA[pperm(j0 + 1)] = to_tf32(oacc[t][1] * invA);
        pB[pperm(j0)]     = to_tf32(oacc[t][2] * invB);
        pB[pperm(j0 + 1)] = to_tf32(oacc[t][3] * invB);
    }
}

// ---------------- launch (fork-join graph) ---------------------------------
extern "C" void kernel_launch(void* const* d_in, const int* in_sizes, int n_in,
                              void* d_out, int out_size)
{
    const float* x    = (const float*)d_in[0];
    const float* pos  = (const float*)d_in[1];
    const float* ln1g = (const float*)d_in[2];
    const float* ln1b = (const float*)d_in[3];
    const float* wqkv = (const float*)d_in[4];
    const float* bqkv = (const float*)d_in[5];
    const float* wo   = (const float*)d_in[6];
    const float* bo   = (const float*)d_in[7];
    const float* ln2g = (const float*)d_in[8];
    const float* ln2b = (const float*)d_in[9];
    const float* wfc  = (const float*)d_in[10];
    const float* bfc  = (const float*)d_in[11];
    const float* wpr  = (const float*)d_in[12];
    const float* bpr  = (const float*)d_in[13];
    float* out = (float*)d_out;

    __nv_bfloat16 *p_qkvh, *p_qkvl;
    float *p_h, *p_at, *p_x2, *p_m, *p_ff, *p_wqkvT, *p_woT, *p_wfcT, *p_wprT;
    cudaGetSymbolAddress((void**)&p_h, g_h);
    cudaGetSymbolAddress((void**)&p_qkvh, g_qkvh);   cudaGetSymbolAddress((void**)&p_qkvl, g_qkvl);
    cudaGetSymbolAddress((void**)&p_at, g_at);
    cudaGetSymbolAddress((void**)&p_x2, g_x2);
    cudaGetSymbolAddress((void**)&p_m, g_m);
    cudaGetSymbolAddress((void**)&p_ff, g_ff);
    cudaGetSymbolAddress((void**)&p_wqkvT, g_wqkvT);
    cudaGetSymbolAddress((void**)&p_woT, g_woT);
    cudaGetSymbolAddress((void**)&p_wfcT, g_wfcT);
    cudaGetSymbolAddress((void**)&p_wprT, g_wprT);

    cudaFuncSetAttribute(tf_gemm<1>, cudaFuncAttributeMaxDynamicSharedMemorySize, TF_SMEM);
    cudaFuncSetAttribute(tf_gemm<2>, cudaFuncAttributeMaxDynamicSharedMemorySize, TF_SMEM);
    cudaFuncSetAttribute(tf_gemm<3>, cudaFuncAttributeMaxDynamicSharedMemorySize, TF_SMEM);
    cudaFuncSetAttribute(attn_kernel, cudaFuncAttributeMaxDynamicSharedMemorySize, ATT_SMEM);

    dim3 tb(32, 8);

    // --- fork: s1 = qkv weight transpose, s2 = other weight transposes -----
    cudaEventRecord(g_ev0, 0);
    cudaStreamWaitEvent(g_s1, g_ev0, 0);
    cudaStreamWaitEvent(g_s2, g_ev0, 0);

    wtrans<<<dim3(3 * DD / 32, DD / 32), tb, 0, g_s1>>>(wqkv, p_wqkvT, DD, 3 * DD);
    wtrans<<<dim3(DD / 32, DD / 32), tb, 0, g_s2>>>(wo, p_woT, DD, DD);
    wtrans<<<dim3(DFFN / 32, DD / 32), tb, 0, g_s2>>>(wfc, p_wfcT, DD, DFFN);
    wtrans<<<dim3(DD / 32, DFFN / 32), tb, 0, g_s2>>>(wpr, p_wprT, DFFN, DD);

    // main stream: LN1 + pos -> tf32 k-permuted
    ln_tf<<<ROWS, 256>>>(x, ln1g, ln1b, pos, p_h);

    // join s1 before qkv GEMM
    cudaEventRecord(g_ev1, g_s1);
    cudaStreamWaitEvent(0, g_ev1, 0);

    // 2) qkv = h @ w_qkv + b_qkv (tf32 1-pass) -> bf16 hi/lo
    tf_gemm<3><<<dim3(3 * DD / 128, ROWS / 128), 256, TF_SMEM>>>(
        p_h, p_wqkvT, bqkv, nullptr, nullptr, p_qkvh, p_qkvl, ROWS, 3 * DD, DD);

    // 3) causal attention -> tf32 fp32, k-permuted
    attn_kernel<<<dim3(SS / 64, HH, BB), 128, ATT_SMEM>>>(p_qkvh, p_qkvl, p_at);

    // join s2 before o-proj
    cudaEventRecord(g_ev2, g_s2);
    cudaStreamWaitEvent(0, g_ev2, 0);

    // 4) x2 = x + attn @ w_o + b_o (tf32)
    tf_gemm<2><<<dim3(DD / 128, ROWS / 128), 256, TF_SMEM>>>(
        p_at, p_woT, bo, x, p_x2, nullptr, nullptr, ROWS, DD, DD);

    // 5) m = LN2(x2) -> tf32 fp32, k-permuted
    ln_tf<<<ROWS, 256>>>(p_x2, ln2g, ln2b, nullptr, p_m);

    // 6) ff = gelu(m @ w_fc + b_fc) (tf32) -> tf32 fp32, k-permuted
    tf_gemm<1><<<dim3(DFFN / 128, ROWS / 128), 256, TF_SMEM>>>(
        p_m, p_wfcT, bfc, nullptr, p_ff, nullptr, nullptr, ROWS, DFFN, DD);

    // 7) out = x2 + ff @ w_proj + b_proj (tf32)
    tf_gemm<2><<<dim3(DD / 128, ROWS / 128), 256, TF_SMEM>>>(
        p_ff, p_wprT, bpr, p_x2, out, nullptr, nullptr, ROWS, DD, DFFN);
}

// round 17
// speedup vs baseline: 1.1408x; 1.0589x over previous
#include <cuda_runtime.h>
#include <cuda_bf16.h>
#include <cuda_fp16.h>
#include <math.h>
#include <stdint.h>

// Problem constants
#define BB   2
#define SS   2048
#define DD   1024
#define HH   16
#define HDIM 64
#define DFFN 4096
#define ROWS (BB * SS)   // 4096

// -------- scratch (static device globals; no allocation) --------
__device__ __align__(16) float  g_h[ROWS * DD];            // tf32, k-permuted
__device__ __align__(16) __half g_qkvh[ROWS * 3 * DD], g_qkvl[ROWS * 3 * DD];
__device__ __align__(16) float  g_at[ROWS * DD];           // tf32, k-permuted
__device__ __align__(16) float  g_x2[ROWS * DD];
__device__ __align__(16) float  g_m[ROWS * DD];            // tf32, k-permuted
__device__ __align__(16) float  g_ff[ROWS * DFFN];         // tf32, k-permuted
__device__ __align__(16) float  g_wqkvT[3 * DD * DD];      // k-permuted
__device__ __align__(16) float  g_woT[DD * DD];            // k-permuted
__device__ __align__(16) float  g_wfcT[DFFN * DD];         // k-permuted
__device__ __align__(16) float  g_wprT[DD * DFFN];         // k-permuted

// -------- side streams/events for graph fork-join (host objects only) ------
static cudaStream_t g_s1 = nullptr, g_s2 = nullptr;
static cudaEvent_t  g_ev0 = nullptr, g_ev1 = nullptr, g_ev2 = nullptr;
struct _StreamInit {
    _StreamInit() {
        cudaStreamCreateWithFlags(&g_s1, cudaStreamNonBlocking);
        cudaStreamCreateWithFlags(&g_s2, cudaStreamNonBlocking);
        cudaEventCreateWithFlags(&g_ev0, cudaEventDisableTiming);
        cudaEventCreateWithFlags(&g_ev1, cudaEventDisableTiming);
        cudaEventCreateWithFlags(&g_ev2, cudaEventDisableTiming);
    }
};
static _StreamInit _stream_init_once;

// ======================= portable PTX helpers ==============================
__device__ __forceinline__ uint32_t smem_u32(const void* p) {
    uint32_t a;
    asm("{ .reg .u64 t; cvta.to.shared.u64 t, %1; cvt.u32.u64 %0, t; }" : "=r"(a) : "l"(p));
    return a;
}

__device__ __forceinline__ void cp_async16(uint32_t saddr, const void* gaddr) {
    asm volatile("cp.async.cg.shared.global [%0], [%1], 16;" :: "r"(saddr), "l"(gaddr));
}
__device__ __forceinline__ void cp_commit() {
    asm volatile("cp.async.commit_group;" ::: "memory");
}
template <int N>
__device__ __forceinline__ void cp_wait() {
    asm volatile("cp.async.wait_group %0;" :: "n"(N) : "memory");
}

__device__ __forceinline__ void ldsm_x4(uint32_t* r, uint32_t addr) {
    asm volatile("ldmatrix.sync.aligned.m8n8.x4.shared.b16 {%0,%1,%2,%3}, [%4];"
        : "=r"(r[0]), "=r"(r[1]), "=r"(r[2]), "=r"(r[3]) : "r"(addr));
}
__device__ __forceinline__ void ldsm_x4_t(uint32_t* r, uint32_t addr) {
    asm volatile("ldmatrix.sync.aligned.m8n8.x4.trans.shared.b16 {%0,%1,%2,%3}, [%4];"
        : "=r"(r[0]), "=r"(r[1]), "=r"(r[2]), "=r"(r[3]) : "r"(addr));
}

// fp16 MMA (f32 accum)
__device__ __forceinline__ void mma_f16(float* c, const uint32_t* a, const uint32_t* b) {
    asm volatile(
        "mma.sync.aligned.m16n8k16.row.col.f32.f16.f16.f32 "
        "{%0,%1,%2,%3}, {%4,%5,%6,%7}, {%8,%9}, {%0,%1,%2,%3};"
        : "+f"(c[0]), "+f"(c[1]), "+f"(c[2]), "+f"(c[3])
        : "r"(a[0]), "r"(a[1]), "r"(a[2]), "r"(a[3]), "r"(b[0]), "r"(b[1]));
}

__device__ __forceinline__ void mma_tf32(float* c, const uint32_t* a, const uint32_t* b) {
    asm volatile(
        "mma.sync.aligned.m16n8k8.row.col.f32.tf32.tf32.f32 "
        "{%0,%1,%2,%3}, {%4,%5,%6,%7}, {%8,%9}, {%0,%1,%2,%3};"
        : "+f"(c[0]), "+f"(c[1]), "+f"(c[2]), "+f"(c[3])
        : "r"(a[0]), "r"(a[1]), "r"(a[2]), "r"(a[3]), "r"(b[0]), "r"(b[1]));
}

__device__ __forceinline__ float to_tf32(float x) {
    uint32_t o;
    asm("cvt.rna.tf32.f32 %0, %1;" : "=r"(o) : "f"(x));
    return __uint_as_float(o);
}

// k-permutation within 8-groups: position 2t holds k=t, position 2t+1 holds k=t+4
__device__ __forceinline__ int pperm(int j) { return ((j & 3) << 1) | (j >> 2); }

// ======================= small math helpers ================================
__device__ __forceinline__ float fexp(float x) {
    float y = fminf(fmaxf(x * 1.4426950408889634f, -126.0f), 126.0f);
    float z = y + 12582912.0f;
    int   n = __float_as_int(z) - 0x4B400000;
    float f = y - (z - 12582912.0f);
    float p = 0.0013333558146f;
    p = fmaf(p, f, 0.0096181291076f);
    p = fmaf(p, f, 0.0555041086648f);
    p = fmaf(p, f, 0.2402265069591f);
    p = fmaf(p, f, 0.6931471805599f);
    p = fmaf(p, f, 1.0f);
    return p * __int_as_float((n + 127) << 23);
}

// gelu (tanh approx) via exact identity: 0.5x(1+tanh z) = x / (1 + e^{-2z})
__device__ __forceinline__ float gelu_fast(float x) {
    float x2 = x * x;
    float z2 = 1.5957691216057308f * fmaf(0.044715f * x2, x, x);  // 2z
    float e = fexp(-z2);
    return __fdividef(x, 1.0f + e);
}

// ============ weight transpose + tf32 round, k-permuted ====================
__global__ void wtrans(const float* __restrict__ W, float* __restrict__ T, int K, int N)
{
    __shared__ float t[32][33];
    int bx = blockIdx.x, by = blockIdx.y;
    int x = threadIdx.x, y = threadIdx.y;
#pragma unroll
    for (int i = 0; i < 32; i += 8)
        t[y + i][x] = W[(size_t)(by * 32 + y + i) * N + bx * 32 + x];
    __syncthreads();
    int kp = by * 32 + (x & ~7) + pperm(x & 7);   // permuted k index
#pragma unroll
    for (int i = 0; i < 32; i += 8)
        T[(size_t)(bx * 32 + y + i) * K + kp] = to_tf32(t[x][y + i]);
}

// -------- LayerNorm (+opt pos) -> tf32-rounded fp32, k-permuted ------------
__global__ void ln_tf(const float* __restrict__ x,
                      const float* __restrict__ gam,
                      const float* __restrict__ bet,
                      const float* __restrict__ pos,
                      float* __restrict__ out)
{
    int row = blockIdx.x;
    int tid = threadIdx.x;
    const float4* xr = (const float4*)(x + (size_t)row * DD);
    float4 v = xr[tid];
    float s  = v.x + v.y + v.z + v.w;
    float ss = v.x * v.x + v.y * v.y + v.z * v.z + v.w * v.w;
#pragma unroll
    for (int o = 16; o > 0; o >>= 1) {
        s  += __shfl_xor_sync(0xffffffffu, s,  o);
        ss += __shfl_xor_sync(0xffffffffu, ss, o);
    }
    __shared__ float sb[8], sb2[8], stats[2];
    int wid = tid >> 5, lane = tid & 31;
    if (lane == 0) { sb[wid] = s; sb2[wid] = ss; }
    __syncthreads();
    if (tid == 0) {
        float ts = 0.f, tss = 0.f;
#pragma unroll
        for (int i = 0; i < 8; i++) { ts += sb[i]; tss += sb2[i]; }
        float mu  = ts  * (1.0f / DD);
        float var = tss * (1.0f / DD) - mu * mu;
        stats[0] = mu;
        stats[1] = rsqrtf(var + 1e-5f);
    }
    __syncthreads();
    float mu = stats[0], rs = stats[1];
    int c = tid * 4;
    float4 gg = *(const float4*)(gam + c);
    float4 bb = *(const float4*)(bet + c);
    float vals[4];
    vals[0] = (v.x - mu) * rs * gg.x + bb.x;
    vals[1] = (v.y - mu) * rs * gg.y + bb.y;
    vals[2] = (v.z - mu) * rs * gg.z + bb.z;
    vals[3] = (v.w - mu) * rs * gg.w + bb.w;
    if (pos) {
        int srow = row % SS;
        float4 p = *(const float4*)(pos + (size_t)srow * DD + c);
        vals[0] += p.x; vals[1] += p.y; vals[2] += p.z; vals[3] += p.w;
    }
    int base = c & ~7, o8 = c & 7;
    float* op = out + (size_t)row * DD + base;
#pragma unroll
    for (int i = 0; i < 4; i++)
        op[pperm(o8 + i)] = to_tf32(vals[i]);
}

// ===== tf32 1-pass GEMM (k-permuted, XOR-swizzled rows, LDS.64 frags) ======
// EPI: 1 = gelu(+bias) -> tf32 fp32 k-permuted ; 2 = +bias+res -> fp32 ;
//      3 = +bias -> fp16 hi (+lo only for q columns c<DD)
#define TTILEB 8192                 // bytes per 128x16 float tile
#define TSTB   (2 * TTILEB)         // bytes per stage (A + B)
#define TSTF   (TSTB / 4)           // floats per stage
#define TF_SMEM (3 * TSTB)          // 49152 bytes

__device__ __forceinline__ void cp_stage_tf(uint32_t sbase,
                                            const float* __restrict__ A,
                                            const float* __restrict__ Bt,
                                            int am0, int bn0, int k0, int ldk, int tid)
{
#pragma unroll
    for (int j = 0; j < 4; j++) {
        int idx = tid + (j << 8);        // 0..1023
        int tile = idx >> 9;
        int w = idx & 511;
        int r = w >> 2, c = w & 3;       // row, 16B chunk
        uint32_t dst = sbase + (uint32_t)tile * TTILEB
                     + (uint32_t)(r * 64) + (uint32_t)(((c ^ (r & 3)) << 4));
        const float* src = (tile ? Bt + (size_t)(bn0 + r) * ldk : A + (size_t)(am0 + r) * ldk)
                           + k0 + c * 4;
        cp_async16(dst, src);
    }
}

template <int EPI>
__global__ __launch_bounds__(256, 2)
void tf_gemm(const float* __restrict__ A, const float* __restrict__ Bt,
             const float* __restrict__ bias, const float* __restrict__ res,
             float* __restrict__ Cf, __half* __restrict__ Chi,
             __half* __restrict__ Clo, int M, int N, int K)
{
    extern __shared__ __align__(128) float smf[];
    int tid = threadIdx.x, wid = tid >> 5, lane = tid & 31;
    int warp_m = wid >> 2, warp_n = wid & 3;     // 2m x 4n
    int g = lane >> 2, tig = lane & 3;
    int bn = blockIdx.x, bm = blockIdx.y;
    int am0 = bm * 128, bn0 = bn * 128;

    float acc[4][4][4];
#pragma unroll
    for (int mi = 0; mi < 4; mi++)
#pragma unroll
        for (int ni = 0; ni < 4; ni++)
#pragma unroll
            for (int q = 0; q < 4; q++) acc[mi][ni][q] = 0.f;

    int nchunk = K >> 4;
    uint32_t sb = smem_u32(smf);
    cp_stage_tf(sb + 0 * TSTB, A, Bt, am0, bn0, 0, K, tid);
    cp_commit();
    cp_stage_tf(sb + 1 * TSTB, A, Bt, am0, bn0, 16, K, tid);
    cp_commit();

    int subo = (tig & 1) * 2;
    int cjt  = tig >> 1;

    int slot = 0;
    for (int ch = 0; ch < nchunk; ch++) {
        cp_wait<1>();
        __syncthreads();
        int nslot = slot + 2; if (nslot >= 3) nslot -= 3;
        if (ch + 2 < nchunk)
            cp_stage_tf(sb + (uint32_t)nslot * TSTB, A, Bt, am0, bn0,
                        (ch + 2) << 4, K, tid);
        cp_commit();

        const float* As = smf + slot * TSTF;
        const float* Bs = As + (TTILEB / 4);

#pragma unroll
        for (int ks = 0; ks < 2; ks++) {
            int cj = ks * 2 + cjt;
            uint32_t a[4][4];
#pragma unroll
            for (int mi = 0; mi < 4; mi++) {
                int r0 = warp_m * 64 + mi * 16 + g;
                int r1 = r0 + 8;
                float2 f0 = *(const float2*)&As[r0 * 16 + ((cj ^ (r0 & 3)) << 2) + subo];
                float2 f1 = *(const float2*)&As[r1 * 16 + ((cj ^ (r1 & 3)) << 2) + subo];
                a[mi][0] = __float_as_uint(f0.x);
                a[mi][1] = __float_as_uint(f1.x);
                a[mi][2] = __float_as_uint(f0.y);
                a[mi][3] = __float_as_uint(f1.y);
            }
            uint32_t b[4][2];
#pragma unroll
            for (int ni = 0; ni < 4; ni++) {
                int rn = warp_n * 32 + ni * 8 + g;
                float2 f = *(const float2*)&Bs[rn * 16 + ((cj ^ (rn & 3)) << 2) + subo];
                b[ni][0] = __float_as_uint(f.x);
                b[ni][1] = __float_as_uint(f.y);
            }
#pragma unroll
            for (int mi = 0; mi < 4; mi++)
#pragma unroll
                for (int ni = 0; ni < 4; ni++)
                    mma_tf32(acc[mi][ni], a[mi], b[ni]);
        }
        slot++; if (slot >= 3) slot = 0;
    }

#pragma unroll
    for (int mi = 0; mi < 4; mi++) {
#pragma unroll
        for (int half = 0; half < 2; half++) {
            int r = bm * 128 + warp_m * 64 + mi * 16 + g + half * 8;
#pragma unroll
            for (int ni = 0; ni < 4; ni++) {
                int c = bn * 128 + warp_n * 32 + ni * 8 + tig * 2;
                float v0 = acc[mi][ni][half * 2 + 0];
                float v1 = acc[mi][ni][half * 2 + 1];
                float2 bv = *(const float2*)(bias + c);
                v0 += bv.x; v1 += bv.y;
                size_t rowb = (size_t)r * N;
                if (EPI == 1) {
                    int cb = c & ~7, j = c & 7;
                    Cf[rowb + cb + pperm(j)]     = to_tf32(gelu_fast(v0));
                    Cf[rowb + cb + pperm(j + 1)] = to_tf32(gelu_fast(v1));
                } else if (EPI == 3) {
                    __half h0 = __float2half_rn(v0), h1 = __float2half_rn(v1);
                    *(__half2*)(Chi + rowb + c) = __halves2half2(h0, h1);
                    if (c < DD) {   // lo needed only for Q columns
                        float l0 = v0 - __half2float(h0);
                        float l1 = v1 - __half2float(h1);
                        *(__half2*)(Clo + rowb + c) =
                            __halves2half2(__float2half_rn(l0), __float2half_rn(l1));
                    }
                } else {
                    float2 rv = *(const float2*)(res + rowb + c);
                    v0 += rv.x; v1 += rv.y;
                    *(float2*)(Cf + rowb + c) = make_float2(v0, v1);
                }
            }
        }
    }
}

// ======= Tensor-core causal flash attention (fp16 2-pass, pipelined) =======
// grid (S/64, H, B), 128 threads (4 warps; warp owns 16 q-rows).
// Q as fp16 hi+lo; K, V single fp16. Passes: S = Qh·Kh + Ql·Kh ;
// O += Ph·Vh + Pl·Vh (P split fp16 in regs). 64 KB smem -> 2 CTAs/SM.
#define AQH 0
#define AQL 8192
#define ASTG 16384
#define SKH 0
#define SVH 8192
#define SSTG 16384
#define ATT_SMEM (ASTG + 3 * SSTG)   // 64 KB

__device__ __forceinline__ void attn_cp_kv(uint32_t stg,
                                           const __half* __restrict__ qh,
                                           size_t rowbase, int hoff, int tid)
{
#pragma unroll
    for (int j = 0; j < 4; j++) {
        int idx = tid + (j << 7);
        int r = idx >> 3, c = idx & 7;
        uint32_t ad = (uint32_t)(r * 128) + (uint32_t)(((c ^ r) & 7) << 4);
        size_t gK = rowbase + (size_t)r * (3 * DD) + DD + hoff + c * 8;
        size_t gV = rowbase + (size_t)r * (3 * DD) + 2 * DD + hoff + c * 8;
        cp_async16(stg + SKH + ad, qh + gK);
        cp_async16(stg + SVH + ad, qh + gV);
    }
}

__global__ __launch_bounds__(128)
void attn_kernel(const __half* __restrict__ qkvh,
                 const __half* __restrict__ qkvl,
                 float* __restrict__ oat)
{
    extern __shared__ __align__(128) char sma[];
    uint32_t sb = smem_u32(sma);
    int qt = (int)gridDim.x - 1 - (int)blockIdx.x;
    int h = blockIdx.y, b = blockIdx.z;
    int tid = threadIdx.x, warp = tid >> 5, lane = tid & 31;
    int q0 = qt * 64;
    int g = lane >> 2, tig = lane & 3;
    int hoff = h * HDIM;

    {
        size_t rowQ = (size_t)(b * SS + q0) * (3 * DD);
#pragma unroll
        for (int j = 0; j < 4; j++) {
            int idx = tid + (j << 7);
            int r = idx >> 3, c = idx & 7;
            uint32_t ad = (uint32_t)(r * 128) + (uint32_t)(((c ^ r) & 7) << 4);
            size_t gQ = rowQ + (size_t)r * (3 * DD) + hoff + c * 8;
            cp_async16(sb + AQH + ad, qkvh + gQ);
            cp_async16(sb + AQL + ad, qkvl + gQ);
        }
        attn_cp_kv(sb + ASTG, qkvh, (size_t)(b * SS) * (3 * DD), hoff, tid);
        cp_commit();
        attn_cp_kv(sb + ASTG + SSTG, qkvh,
                   (size_t)(b * SS + 64) * (3 * DD), hoff, tid);
        cp_commit();
    }

    int lrA = (lane & 7) + ((lane >> 3) & 1) * 8;
    uint32_t cA = (uint32_t)((lane >> 4) << 4);
    int rowA = warp * 16 + lrA;
    uint32_t aBase = (uint32_t)(rowA * 128);
    uint32_t aMask = (uint32_t)((rowA & 7) << 4);

    int lrB = (lane & 7) + ((lane >> 4) & 1) * 8;
    uint32_t cB = (uint32_t)(((lane >> 3) & 1) << 4);

    int lrV = (lane & 7) + ((lane >> 3) & 1) * 8;
    uint32_t cV = (uint32_t)(((lane >> 4) & 1) << 4);

    float oacc[8][4];
    float mA = -1e30f, mB = -1e30f, lA = 0.f, lB = 0.f;
#pragma unroll
    for (int t = 0; t < 8; t++)
#pragma unroll
        for (int q = 0; q < 4; q++) oacc[t][q] = 0.f;

    int slot = 0;
    for (int kt = 0; kt <= qt; kt++) {
        uint32_t st = sb + ASTG + (uint32_t)slot * SSTG;
        cp_wait<1>();
        __syncthreads();
        int nslot = slot + 2; if (nslot >= 3) nslot -= 3;
        if (kt + 2 <= qt)
            attn_cp_kv(sb + ASTG + (uint32_t)nslot * SSTG, qkvh,
                       (size_t)(b * SS + (kt + 2) * 64) * (3 * DD), hoff, tid);
        cp_commit();

        // ---- S = Q K^T (fp16 2-pass) ----
        float sacc[8][4];
#pragma unroll
        for (int t = 0; t < 8; t++)
#pragma unroll
            for (int q = 0; q < 4; q++) sacc[t][q] = 0.f;

#pragma unroll
        for (int ks = 0; ks < 4; ks++) {
            uint32_t kx = (uint32_t)(ks * 32);
            uint32_t qh4[4], ql4[4], kh[8][2];
            ldsm_x4(qh4, sb + AQH + aBase + ((kx + cA) ^ aMask));
            ldsm_x4(ql4, sb + AQL + aBase + ((kx + cA) ^ aMask));
#pragma unroll
            for (int p = 0; p < 4; p++) {
                int rowB = p * 16 + lrB;
                uint32_t r4[4];
                ldsm_x4(r4, st + SKH + (uint32_t)(rowB * 128) +
                            ((kx + cB) ^ (uint32_t)((rowB & 7) << 4)));
                kh[2 * p][0] = r4[0]; kh[2 * p][1] = r4[1];
                kh[2 * p + 1][0] = r4[2]; kh[2 * p + 1][1] = r4[3];
            }
#pragma unroll
            for (int t = 0; t < 8; t++) mma_f16(sacc[t], qh4, kh[t]);
#pragma unroll
            for (int t = 0; t < 8; t++) mma_f16(sacc[t], ql4, kh[t]);
        }

#pragma unroll
        for (int t = 0; t < 8; t++) {
            sacc[t][0] *= 0.125f; sacc[t][1] *= 0.125f;
            sacc[t][2] *= 0.125f; sacc[t][3] *= 0.125f;
        }

        if (kt == qt) {
            int qlocA = warp * 16 + g, qlocB = qlocA + 8;
#pragma unroll
            for (int t = 0; t < 8; t++) {
                int k0c = t * 8 + tig * 2;
                if (k0c > qlocA)     sacc[t][0] = -1e30f;
                if (k0c + 1 > qlocA) sacc[t][1] = -1e30f;
                if (k0c > qlocB)     sacc[t][2] = -1e30f;
                if (k0c + 1 > qlocB) sacc[t][3] = -1e30f;
            }
        }

        // ---- online softmax ----
        float maA = -1e30f, maB = -1e30f;
#pragma unroll
        for (int t = 0; t < 8; t++) {
            maA = fmaxf(maA, fmaxf(sacc[t][0], sacc[t][1]));
            maB = fmaxf(maB, fmaxf(sacc[t][2], sacc[t][3]));
        }
        maA = fmaxf(maA, __shfl_xor_sync(0xffffffffu, maA, 1));
        maA = fmaxf(maA, __shfl_xor_sync(0xffffffffu, maA, 2));
        maB = fmaxf(maB, __shfl_xor_sync(0xffffffffu, maB, 1));
        maB = fmaxf(maB, __shfl_xor_sync(0xffffffffu, maB, 2));
        float nmA = fmaxf(mA, maA), nmB = fmaxf(mB, maB);
        float corrA = fexp(mA - nmA), corrB = fexp(mB - nmB);
        mA = nmA; mB = nmB;
        float sumA = 0.f, sumB = 0.f;
#pragma unroll
        for (int t = 0; t < 8; t++) {
            sacc[t][0] = fexp(sacc[t][0] - nmA);
            sacc[t][1] = fexp(sacc[t][1] - nmA);
            sacc[t][2] = fexp(sacc[t][2] - nmB);
            sacc[t][3] = fexp(sacc[t][3] - nmB);
            sumA += sacc[t][0] + sacc[t][1];
            sumB += sacc[t][2] + sacc[t][3];
        }
        sumA += __shfl_xor_sync(0xffffffffu, sumA, 1);
        sumA += __shfl_xor_sync(0xffffffffu, sumA, 2);
        sumB += __shfl_xor_sync(0xffffffffu, sumB, 1);
        sumB += __shfl_xor_sync(0xffffffffu, sumB, 2);
        lA = lA * corrA + sumA;
        lB = lB * corrB + sumB;
#pragma unroll
        for (int t = 0; t < 8; t++) {
            oacc[t][0] *= corrA; oacc[t][1] *= corrA;
            oacc[t][2] *= corrB; oacc[t][3] *= corrB;
        }

        // ---- pack P into fp16 A-fragments (hi + lo) ----
        uint32_t ph[4][4], pl[4][4];
#pragma unroll
        for (int p = 0; p < 4; p++) {
#pragma unroll
            for (int q = 0; q < 4; q++) {
                int t = 2 * p + (q >> 1);
                float a = sacc[t][(q & 1) * 2 + 0];
                float bv = sacc[t][(q & 1) * 2 + 1];
                __half ah2 = __float2half_rn(a), bh2 = __float2half_rn(bv);
                __half2 th = __halves2half2(ah2, bh2);
                ph[p][q] = *(uint32_t*)&th;
                __half2 tl = __halves2half2(
                    __float2half_rn(a - __half2float(ah2)),
                    __float2half_rn(bv - __half2float(bh2)));
                pl[p][q] = *(uint32_t*)&tl;
            }
        }

        // ---- O += P V (fp16 2-pass) ----
#pragma unroll
        for (int ks = 0; ks < 4; ks++) {
            int rowV = ks * 16 + lrV;
            uint32_t vMask = (uint32_t)((rowV & 7) << 4);
            uint32_t vbh[8][2];
#pragma unroll
            for (int j = 0; j < 4; j++) {
                uint32_t cb = (uint32_t)(j * 32) + cV;
                uint32_t r4[4];
                ldsm_x4_t(r4, st + SVH + (uint32_t)(rowV * 128) + (cb ^ vMask));
                vbh[2 * j][0] = r4[0]; vbh[2 * j][1] = r4[1];
                vbh[2 * j + 1][0] = r4[2]; vbh[2 * j + 1][1] = r4[3];
            }
#pragma unroll
            for (int t = 0; t < 8; t++) mma_f16(oacc[t], ph[ks], vbh[t]);
#pragma unroll
            for (int t = 0; t < 8; t++) mma_f16(oacc[t], pl[ks], vbh[t]);
        }
        slot++; if (slot >= 3) slot = 0;
    }

    // ---- normalize + k-permuted write (feeds o-proj tf32 GEMM) ----
    float invA = 1.0f / lA, invB = 1.0f / lB;
    int rowAg = b * SS + q0 + warp * 16 + g;
    int rowBg = rowAg + 8;
#pragma unroll
    for (int t = 0; t < 8; t++) {
        int gbase = h * HDIM + t * 8;
        int j0 = tig * 2;
        float* pA = oat + (size_t)rowAg * DD + gbase;
        float* pB = oat + (size_t)rowBg * DD + gbase;
        pA[pperm(j0)]     = to_tf32(oacc[t][0] * invA);
        pA[pperm(j0 + 1)] = to_tf32(oacc[t][1] * invA);
        pB[pperm(j0)]     = to_tf32(oacc[t][2] * invB);
        pB[pperm(j0 + 1)] = to_tf32(oacc[t][3] * invB);
    }
}

// ---------------- launch (fork-join graph) ---------------------------------
extern "C" void kernel_launch(void* const* d_in, const int* in_sizes, int n_in,
                              void* d_out, int out_size)
{
    const float* x    = (const float*)d_in[0];
    const float* pos  = (const float*)d_in[1];
    const float* ln1g = (const float*)d_in[2];
    const float* ln1b = (const float*)d_in[3];
    const float* wqkv = (const float*)d_in[4];
    const float* bqkv = (const float*)d_in[5];
    const float* wo   = (const float*)d_in[6];
    const float* bo   = (const float*)d_in[7];
    const float* ln2g = (const float*)d_in[8];
    const float* ln2b = (const float*)d_in[9];
    const float* wfc  = (const float*)d_in[10];
    const float* bfc  = (const float*)d_in[11];
    const float* wpr  = (const float*)d_in[12];
    const float* bpr  = (const float*)d_in[13];
    float* out = (float*)d_out;

    __half *p_qkvh, *p_qkvl;
    float *p_h, *p_at, *p_x2, *p_m, *p_ff, *p_wqkvT, *p_woT, *p_wfcT, *p_wprT;
    cudaGetSymbolAddress((void**)&p_h, g_h);
    cudaGetSymbolAddress((void**)&p_qkvh, g_qkvh);   cudaGetSymbolAddress((void**)&p_qkvl, g_qkvl);
    cudaGetSymbolAddress((void**)&p_at, g_at);
    cudaGetSymbolAddress((void**)&p_x2, g_x2);
    cudaGetSymbolAddress((void**)&p_m, g_m);
    cudaGetSymbolAddress((void**)&p_ff, g_ff);
    cudaGetSymbolAddress((void**)&p_wqkvT, g_wqkvT);
    cudaGetSymbolAddress((void**)&p_woT, g_woT);
    cudaGetSymbolAddress((void**)&p_wfcT, g_wfcT);
    cudaGetSymbolAddress((void**)&p_wprT, g_wprT);

    cudaFuncSetAttribute(tf_gemm<1>, cudaFuncAttributeMaxDynamicSharedMemorySize, TF_SMEM);
    cudaFuncSetAttribute(tf_gemm<2>, cudaFuncAttributeMaxDynamicSharedMemorySize, TF_SMEM);
    cudaFuncSetAttribute(tf_gemm<3>, cudaFuncAttributeMaxDynamicSharedMemorySize, TF_SMEM);
    cudaFuncSetAttribute(attn_kernel, cudaFuncAttributeMaxDynamicSharedMemorySize, ATT_SMEM);

    dim3 tb(32, 8);

    // --- fork: s1 = qkv weight transpose, s2 = other weight transposes -----
    cudaEventRecord(g_ev0, 0);
    cudaStreamWaitEvent(g_s1, g_ev0, 0);
    cudaStreamWaitEvent(g_s2, g_ev0, 0);

    wtrans<<<dim3(3 * DD / 32, DD / 32), tb, 0, g_s1>>>(wqkv, p_wqkvT, DD, 3 * DD);
    wtrans<<<dim3(DD / 32, DD / 32), tb, 0, g_s2>>>(wo, p_woT, DD, DD);
    wtrans<<<dim3(DFFN / 32, DD / 32), tb, 0, g_s2>>>(wfc, p_wfcT, DD, DFFN);
    wtrans<<<dim3(DD / 32, DFFN / 32), tb, 0, g_s2>>>(wpr, p_wprT, DFFN, DD);

    // main stream: LN1 + pos -> tf32 k-permuted
    ln_tf<<<ROWS, 256>>>(x, ln1g, ln1b, pos, p_h);

    // join s1 before qkv GEMM
    cudaEventRecord(g_ev1, g_s1);
    cudaStreamWaitEvent(0, g_ev1, 0);

    // 2) qkv = h @ w_qkv + b_qkv (tf32 1-pass) -> fp16 hi (+lo for q)
    tf_gemm<3><<<dim3(3 * DD / 128, ROWS / 128), 256, TF_SMEM>>>(
        p_h, p_wqkvT, bqkv, nullptr, nullptr, p_qkvh, p_qkvl, ROWS, 3 * DD, DD);

    // 3) causal attention (fp16 2-pass) -> tf32 fp32, k-permuted
    attn_kernel<<<dim3(SS / 64, HH, BB), 128, ATT_SMEM>>>(p_qkvh, p_qkvl, p_at);

    // join s2 before o-proj
    cudaEventRecord(g_ev2, g_s2);
    cudaStreamWaitEvent(0, g_ev2, 0);

    // 4) x2 = x + attn @ w_o + b_o (tf32)
    tf_gemm<2><<<dim3(DD / 128, ROWS / 128), 256, TF_SMEM>>>(
        p_at, p_woT, bo, x, p_x2, nullptr, nullptr, ROWS, DD, DD);

    // 5) m = LN2(x2) -> tf32 fp32, k-permuted
    ln_tf<<<ROWS, 256>>>(p_x2, ln2g, ln2b, nullptr, p_m);

    // 6) ff = gelu(m @ w_fc + b_fc) (tf32) -> tf32 fp32, k-permuted
    tf_gemm<1><<<dim3(DFFN / 128, ROWS / 128), 256, TF_SMEM>>>(
        p_m, p_wfcT, bfc, nullptr, p_ff, nullptr, nullptr, ROWS, DFFN, DD);

    // 7) out = x2 + ff @ w_proj + b_proj (tf32)
    tf_gemm<2><<<dim3(DD / 128, ROWS / 128), 256, TF_SMEM>>>(
        p_ff, p_wprT, bpr, p_x2, out, nullptr, nullptr, ROWS, DD, DFFN);
}